// round 2
// baseline (speedup 1.0000x reference)
#include <cuda_runtime.h>
#include <math.h>

// ---------------- scratch (device globals: allocation-free rule) ----------------
__device__ float g_h1[32u * 64 * 128 * 128];   // after conv1+relu   (NCHW)
__device__ float g_h2[32u * 128 * 64 * 64];    // after conv2+relu   (NCHW)
__device__ float g_z [32u * 64 * 64 * 64];     // after conv3+relu   (NHWC: [131072,64])
__device__ float g_q [32u * 64 * 64 * 64];     // quantized          (NHWC)
__device__ float g_d1[32u * 128 * 128 * 128];  // after deconv1+relu (NCHW)
__device__ float g_d2[32u * 64 * 256 * 256];   // after deconv2+relu (NCHW)

// repacked weights: layout [(ci*KK + t) * CO + co]
__device__ float g_wt1 [64 * 3 * 16];
__device__ float g_wt2 [128 * 64 * 16];
__device__ float g_wt3 [64 * 128 * 9];
__device__ float g_dwt1[128 * 64 * 16];
__device__ float g_dwt2[64 * 128 * 16];
__device__ float g_dwt3[3 * 64 * 9];

__device__ float g_loss;

// ---------------- weight repack ----------------
// conv weight OIHW: w[co][ci][t]  -> wt[(ci*KK+t)*Co + co]
__global__ void repack_conv(const float* __restrict__ w, float* __restrict__ wt,
                            int Co, int Ci, int KK) {
    int i = blockIdx.x * blockDim.x + threadIdx.x;
    int total = Co * Ci * KK;
    if (i >= total) return;
    int co = i / (Ci * KK);
    int r  = i % (Ci * KK);
    wt[r * Co + co] = w[i];
}
// deconv weight [ci][co][t] -> wt[(ci*KK+t)*Co + co]
__global__ void repack_deconv(const float* __restrict__ w, float* __restrict__ wt,
                              int Co, int Ci, int KK) {
    int i = blockIdx.x * blockDim.x + threadIdx.x;
    int total = Ci * Co * KK;
    if (i >= total) return;
    int ci = i / (Co * KK);
    int r  = i % (Co * KK);
    int co = r / KK;
    int t  = r % KK;
    wt[(ci * KK + t) * Co + co] = w[i];
}

__global__ void zero_loss_k() { g_loss = 0.0f; }

__global__ void finalize_k(float* __restrict__ out, int loss_idx) {
    out[loss_idx] = 1.25f * g_loss * (1.0f / 8388608.0f);
}

// ---------------- direct conv + relu ----------------
// one thread = one (b,ho,wo), COT output channels. weights in smem (broadcast LDS).
template<int CI, int K, int CO, int COT, int HIN, int WIN, int HOUT, int WOUT,
         int ST, int PD, bool NHWC_OUT>
__global__ void conv_relu_k(const float* __restrict__ in, const float* __restrict__ wt,
                            const float* __restrict__ bias, float* __restrict__ out) {
    extern __shared__ float ws[];                   // [CI*K*K][COT]
    const int cob = blockIdx.y * COT;
    const int WROWS = CI * K * K;
    for (int i = threadIdx.x; i < WROWS * COT; i += blockDim.x) {
        int r = i / COT, c = i % COT;
        ws[r * COT + c] = wt[r * CO + cob + c];
    }
    __syncthreads();

    int s  = blockIdx.x * blockDim.x + threadIdx.x;
    int wo = s % WOUT;
    int t  = s / WOUT;
    int ho = t % HOUT;
    int b  = t / HOUT;

    float acc[COT];
#pragma unroll
    for (int c = 0; c < COT; c++) acc[c] = bias[cob + c];

    const float* inb = in + (size_t)b * CI * HIN * WIN;
    for (int ci = 0; ci < CI; ci++) {
        const float* inp = inb + (size_t)ci * HIN * WIN;
#pragma unroll
        for (int kh = 0; kh < K; kh++) {
            int hi = ho * ST - PD + kh;
            if ((unsigned)hi >= (unsigned)HIN) continue;
#pragma unroll
            for (int kw = 0; kw < K; kw++) {
                int wi = wo * ST - PD + kw;
                if ((unsigned)wi >= (unsigned)WIN) continue;
                float v = inp[hi * WIN + wi];
                const float* wr = ws + (ci * (K * K) + kh * K + kw) * COT;
#pragma unroll
                for (int c = 0; c < COT; c++) acc[c] += v * wr[c];
            }
        }
    }

    if (NHWC_OUT) {
        size_t ob = (((size_t)b * HOUT + ho) * WOUT + wo) * CO + cob;
#pragma unroll
        for (int c = 0; c < COT; c++) {
            float v = acc[c];
            out[ob + c] = v > 0.0f ? v : 0.0f;
        }
    } else {
        size_t ob = ((size_t)b * CO + cob) * HOUT * WOUT + (size_t)ho * WOUT + wo;
#pragma unroll
        for (int c = 0; c < COT; c++) {
            float v = acc[c];
            out[ob + (size_t)c * HOUT * WOUT] = v > 0.0f ? v : 0.0f;
        }
    }
}

// ---------------- transposed conv + activation (0=relu, 1=sigmoid) ----------------
template<int CI, int K, int CO, int COT, int HIN, int WIN, int HOUT, int WOUT,
         int ST, int PD, bool NHWC_IN, int ACT>
__global__ void deconv_act_k(const float* __restrict__ in, const float* __restrict__ wt,
                             const float* __restrict__ bias, float* __restrict__ out) {
    extern __shared__ float ws[];                   // [CI*K*K][COT]
    const int cob = blockIdx.y * COT;
    const int WROWS = CI * K * K;
    for (int i = threadIdx.x; i < WROWS * COT; i += blockDim.x) {
        int r = i / COT, c = i % COT;
        ws[r * COT + c] = wt[r * CO + cob + c];
    }
    __syncthreads();

    int s  = blockIdx.x * blockDim.x + threadIdx.x;
    int wo = s % WOUT;
    int t  = s / WOUT;
    int ho = t % HOUT;
    int b  = t / HOUT;

    float acc[COT];
#pragma unroll
    for (int c = 0; c < COT; c++) acc[c] = bias[cob + c];

#pragma unroll
    for (int kh = 0; kh < K; kh++) {
        int hn = ho + PD - kh;
        if (hn % ST) continue;
        int hi = hn / ST;
        if ((unsigned)hi >= (unsigned)HIN) continue;
#pragma unroll
        for (int kw = 0; kw < K; kw++) {
            int wn = wo + PD - kw;
            if (wn % ST) continue;
            int wi = wn / ST;
            if ((unsigned)wi >= (unsigned)WIN) continue;

            if (NHWC_IN) {
                const float* ip = in + (((size_t)b * HIN + hi) * WIN + wi) * CI;
                for (int ci = 0; ci < CI; ci++) {
                    float v = ip[ci];
                    const float* wr = ws + (ci * (K * K) + kh * K + kw) * COT;
#pragma unroll
                    for (int c = 0; c < COT; c++) acc[c] += v * wr[c];
                }
            } else {
                const float* ip = in + (size_t)b * CI * HIN * WIN + (size_t)hi * WIN + wi;
                for (int ci = 0; ci < CI; ci++) {
                    float v = ip[(size_t)ci * HIN * WIN];
                    const float* wr = ws + (ci * (K * K) + kh * K + kw) * COT;
#pragma unroll
                    for (int c = 0; c < COT; c++) acc[c] += v * wr[c];
                }
            }
        }
    }

    size_t ob = ((size_t)b * CO + cob) * HOUT * WOUT + (size_t)ho * WOUT + wo;
#pragma unroll
    for (int c = 0; c < COT; c++) {
        float v = acc[c];
        if (ACT == 0) v = v > 0.0f ? v : 0.0f;
        else          v = 1.0f / (1.0f + expf(-v));
        out[ob + (size_t)c * HOUT * WOUT] = v;
    }
}

// ---------------- vector quantize ----------------
// one thread per latent vector (131072 total). codebook + norms in smem.
__global__ void vq_k(const float* __restrict__ emb, const float* __restrict__ z,
                     float* __restrict__ q) {
    extern __shared__ float sm[];
    float* se = sm;              // 512*64 codebook
    float* sn = sm + 512 * 64;   // 512 norms
    for (int i = threadIdx.x; i < 512 * 64; i += blockDim.x) se[i] = emb[i];
    __syncthreads();
    for (int k = threadIdx.x; k < 512; k += blockDim.x) {
        float s = 0.0f;
#pragma unroll
        for (int j = 0; j < 64; j++) { float e = se[k * 64 + j]; s += e * e; }
        sn[k] = s;
    }
    __syncthreads();

    int n = blockIdx.x * blockDim.x + threadIdx.x;
    float zr[64];
    const float* zp = z + (size_t)n * 64;
#pragma unroll
    for (int j = 0; j < 64; j++) zr[j] = zp[j];

    float best = 3.4e38f;
    int bi = 0;
    for (int k = 0; k < 512; k++) {
        const float4* e4 = reinterpret_cast<const float4*>(se + k * 64);
        float dot = 0.0f;
#pragma unroll
        for (int j = 0; j < 16; j++) {
            float4 e = e4[j];
            dot += zr[4 * j]     * e.x;
            dot += zr[4 * j + 1] * e.y;
            dot += zr[4 * j + 2] * e.z;
            dot += zr[4 * j + 3] * e.w;
        }
        float d = sn[k] - 2.0f * dot;     // + ||z||^2 is constant per row
        if (d < best) { best = d; bi = k; }
    }

    float* qp = q + (size_t)n * 64;
    float ls = 0.0f;
#pragma unroll
    for (int j = 0; j < 64; j++) {
        float e = se[bi * 64 + j];
        qp[j] = e;
        float df = e - zr[j];
        ls += df * df;
    }
#pragma unroll
    for (int o = 16; o > 0; o >>= 1) ls += __shfl_xor_sync(0xffffffffu, ls, o);
    if ((threadIdx.x & 31) == 0) atomicAdd(&g_loss, ls);
}

// ---------------- host ----------------
static float* sym_addr(const void* sym) {
    void* p = nullptr;
    cudaGetSymbolAddress(&p, sym);
    return (float*)p;
}

extern "C" void kernel_launch(void* const* d_in, const int* in_sizes, int n_in,
                              void* d_out, int out_size) {
    const float* x   = (const float*)d_in[0];
    const float* w1  = (const float*)d_in[1];
    const float* b1  = (const float*)d_in[2];
    const float* w2  = (const float*)d_in[3];
    const float* b2  = (const float*)d_in[4];
    const float* w3  = (const float*)d_in[5];
    const float* b3  = (const float*)d_in[6];
    const float* emb = (const float*)d_in[7];
    const float* dw1 = (const float*)d_in[8];
    const float* db1 = (const float*)d_in[9];
    const float* dw2 = (const float*)d_in[10];
    const float* db2 = (const float*)d_in[11];
    const float* dw3 = (const float*)d_in[12];
    const float* db3 = (const float*)d_in[13];
    float* out = (float*)d_out;

    float* h1  = sym_addr(g_h1);
    float* h2  = sym_addr(g_h2);
    float* z   = sym_addr(g_z);
    float* q   = sym_addr(g_q);
    float* d1  = sym_addr(g_d1);
    float* d2  = sym_addr(g_d2);
    float* wt1 = sym_addr(g_wt1);
    float* wt2 = sym_addr(g_wt2);
    float* wt3 = sym_addr(g_wt3);
    float* dt1 = sym_addr(g_dwt1);
    float* dt2 = sym_addr(g_dwt2);
    float* dt3 = sym_addr(g_dwt3);

    // opt in to large dynamic smem
    auto c2 = conv_relu_k<64, 4, 128, 32, 128, 128, 64, 64, 2, 1, false>;
    auto c3 = conv_relu_k<128, 3, 64, 32, 64, 64, 64, 64, 1, 1, true>;
    auto dc1 = deconv_act_k<64, 4, 128, 32, 64, 64, 128, 128, 2, 1, true, 0>;
    auto dc2 = deconv_act_k<128, 4, 64, 16, 128, 128, 256, 256, 2, 1, false, 0>;
    cudaFuncSetAttribute(c2,  cudaFuncAttributeMaxDynamicSharedMemorySize, 64 * 16 * 32 * 4);
    cudaFuncSetAttribute(c3,  cudaFuncAttributeMaxDynamicSharedMemorySize, 128 * 9 * 32 * 4);
    cudaFuncSetAttribute(dc1, cudaFuncAttributeMaxDynamicSharedMemorySize, 64 * 16 * 32 * 4);
    cudaFuncSetAttribute(dc2, cudaFuncAttributeMaxDynamicSharedMemorySize, 128 * 16 * 16 * 4);
    cudaFuncSetAttribute(vq_k, cudaFuncAttributeMaxDynamicSharedMemorySize, (512 * 64 + 512) * 4);

    // repack weights
    repack_conv<<<(64 * 3 * 16 + 255) / 256, 256>>>(w1, wt1, 64, 3, 16);
    repack_conv<<<(128 * 64 * 16 + 255) / 256, 256>>>(w2, wt2, 128, 64, 16);
    repack_conv<<<(64 * 128 * 9 + 255) / 256, 256>>>(w3, wt3, 64, 128, 9);
    repack_deconv<<<(64 * 128 * 16 + 255) / 256, 256>>>(dw1, dt1, 128, 64, 16);
    repack_deconv<<<(128 * 64 * 16 + 255) / 256, 256>>>(dw2, dt2, 64, 128, 16);
    repack_deconv<<<(64 * 3 * 9 + 255) / 256, 256>>>(dw3, dt3, 3, 64, 9);
    zero_loss_k<<<1, 1>>>();

    // encoder
    conv_relu_k<3, 4, 64, 32, 256, 256, 128, 128, 2, 1, false>
        <<<dim3(32u * 128 * 128 / 256, 2), 256, 3 * 16 * 32 * 4>>>(x, wt1, b1, h1);
    c2<<<dim3(32u * 64 * 64 / 256, 4), 256, 64 * 16 * 32 * 4>>>(h1, wt2, b2, h2);
    c3<<<dim3(32u * 64 * 64 / 256, 2), 256, 128 * 9 * 32 * 4>>>(h2, wt3, b3, z);

    // vector quantize
    vq_k<<<131072 / 256, 256, (512 * 64 + 512) * 4>>>(emb, z, q);

    // decoder
    dc1<<<dim3(32u * 128 * 128 / 256, 4), 256, 64 * 16 * 32 * 4>>>(q, dt1, db1, d1);
    dc2<<<dim3(32u * 256 * 256 / 256, 4), 256, 128 * 16 * 16 * 4>>>(d1, dt2, db2, d2);
    deconv_act_k<64, 3, 3, 3, 256, 256, 256, 256, 1, 1, false, 1>
        <<<dim3(32u * 256 * 256 / 256, 1), 256, 64 * 9 * 3 * 4>>>(d2, dt3, db3, out);

    finalize_k<<<1, 1>>>(out, out_size - 1);
}

// round 3
// speedup vs baseline: 4.7053x; 4.7053x over previous
#include <cuda_runtime.h>
#include <math.h>

// ---------------- scratch (device globals: allocation-free rule) ----------------
__device__ float g_h1[32u * 64 * 128 * 128];   // after conv1+relu   (NCHW)
__device__ float g_h2[32u * 128 * 64 * 64];    // after conv2+relu   (NCHW)
__device__ float g_z [32u * 64 * 64 * 64];     // after conv3+relu   (NCHW)
__device__ float g_q [32u * 64 * 64 * 64];     // quantized          (NCHW)
__device__ float g_d1[32u * 128 * 128 * 128];  // after deconv1+relu (NCHW)
__device__ float g_d2[32u * 64 * 256 * 256];   // after deconv2+relu (NCHW)
__device__ int   g_idx[32 * 64 * 64];

// repacked weights
__device__ float g_wt1 [64 * 3 * 16];      // [(ci*16+t)*64+co]
__device__ float g_wt2 [128 * 64 * 16];
__device__ float g_wt3 [64 * 128 * 9];
__device__ float g_pw1 [4 * 64 * 4 * 128]; // [((p*CI+ci)*4+tap)*CO+co]
__device__ float g_pw2 [4 * 128 * 4 * 64];
__device__ float g_wt3d[3 * 64 * 9];       // flipped dc3 -> plain conv

__device__ float g_loss;

// ---------------- f32x2 helpers ----------------
__device__ __forceinline__ unsigned long long pk2(float x) {
    unsigned long long r;
    asm("mov.b64 %0, {%1, %1};" : "=l"(r) : "f"(x));
    return r;
}
__device__ __forceinline__ unsigned long long pk(float x, float y) {
    unsigned long long r;
    asm("mov.b64 %0, {%1, %2};" : "=l"(r) : "f"(x), "f"(y));
    return r;
}
__device__ __forceinline__ void fma2(unsigned long long& d,
                                     unsigned long long a, unsigned long long b) {
    asm("fma.rn.f32x2 %0, %1, %2, %0;" : "+l"(d) : "l"(a), "l"(b));
}
__device__ __forceinline__ float2 up2(unsigned long long v) {
    float2 f;
    asm("mov.b64 {%0, %1}, %2;" : "=f"(f.x), "=f"(f.y) : "l"(v));
    return f;
}

// ---------------- weight repack ----------------
// conv weight OIHW: w[co][ci][t] -> wt[(ci*KK+t)*Co + co]
__global__ void repack_conv(const float* __restrict__ w, float* __restrict__ wt,
                            int Co, int Ci, int KK) {
    int i = blockIdx.x * blockDim.x + threadIdx.x;
    if (i >= Co * Ci * KK) return;
    int co = i / (Ci * KK);
    int r  = i % (Ci * KK);
    wt[r * Co + co] = w[i];
}
// stride-1 deconv: flip spatially -> plain conv weights [(ci*9+tflip)*Co+co]
__global__ void repack_deconv_flip(const float* __restrict__ w, float* __restrict__ wt,
                                   int Co, int Ci, int K) {
    int KK = K * K;
    int i = blockIdx.x * blockDim.x + threadIdx.x;
    if (i >= Ci * Co * KK) return;
    int ci = i / (Co * KK);
    int r  = i % (Co * KK);
    int co = r / KK;
    int t  = r % KK;
    int kh = t / K, kw = t % K;
    int tf = (K - 1 - kh) * K + (K - 1 - kw);
    wt[(ci * KK + tf) * Co + co] = w[i];
}
// stride-2 deconv parity decomposition: wp[((p*CI+ci)*4 + a*2+bt)*CO + co]
__global__ void repack_par(const float* __restrict__ w, float* __restrict__ wp,
                           int CI, int CO) {
    int i = blockIdx.x * blockDim.x + threadIdx.x;
    int total = 4 * CI * 4 * CO;
    if (i >= total) return;
    int p  = i / (CI * 4 * CO);
    int r  = i % (CI * 4 * CO);
    int ci = r / (4 * CO);
    int r2 = r % (4 * CO);
    int tap = r2 / CO;
    int co  = r2 % CO;
    int a = tap >> 1, bt = tap & 1;
    int ph = p >> 1, pw = p & 1;
    int kh = ph ? (a ? 0 : 2) : (a ? 3 : 1);
    int kw = pw ? (bt ? 0 : 2) : (bt ? 3 : 1);
    wp[i] = w[((ci * CO + co) * 4 + kh) * 4 + kw];
}

__global__ void zero_loss_k() { g_loss = 0.0f; }
__global__ void finalize_k(float* __restrict__ out, int loss_idx) {
    out[loss_idx] = 1.25f * g_loss * (1.0f / 8388608.0f);
}

// ---------------- conv + relu, f32x2 channel pairs, WT spatial blocking ----------------
// block = 256 threads = 8 warps; each warp = one segment of 32*WT outputs in a row.
template<int CI, int K, int CO, int COT, int WT,
         int HIN, int WIN, int HOUT, int WOUT, int ST, int PD>
__global__ void conv_f2_k(const float* __restrict__ in, const float* __restrict__ wt,
                          const float* __restrict__ bias, float* __restrict__ out) {
    extern __shared__ float ws[];                   // [CI*K*K][COT]
    const int cob = blockIdx.y * COT;
    const int WROWS = CI * K * K;
    for (int i = threadIdx.x; i < WROWS * COT; i += 256) {
        int r = i / COT, c = i % COT;
        ws[i] = wt[r * CO + cob + c];
    }
    __syncthreads();

    const int warp = threadIdx.x >> 5, lane = threadIdx.x & 31;
    const int SPR = WOUT / (32 * WT);
    int seg = blockIdx.x * 8 + warp;
    int s   = seg % SPR;
    int row = seg / SPR;
    int h   = row % HOUT;
    int b   = row / HOUT;

    int wcol[WT];
#pragma unroll
    for (int k = 0; k < WT; k++) wcol[k] = s * 32 * WT + lane + 32 * k;

    unsigned long long acc[WT][COT / 2];
#pragma unroll
    for (int k = 0; k < WT; k++)
#pragma unroll
        for (int j = 0; j < COT / 2; j++)
            acc[k][j] = pk(bias[cob + 2 * j], bias[cob + 2 * j + 1]);

    const float* inb = in + (size_t)b * CI * HIN * WIN;
#pragma unroll 2
    for (int ci = 0; ci < CI; ci++) {
        const float* inp = inb + (size_t)ci * HIN * WIN;
#pragma unroll
        for (int kh = 0; kh < K; kh++) {
            int hi = h * ST - PD + kh;
            if ((unsigned)hi >= (unsigned)HIN) continue;     // uniform per warp
            const float* rp = inp + hi * WIN;
#pragma unroll
            for (int kw = 0; kw < K; kw++) {
                const ulonglong2* wv = reinterpret_cast<const ulonglong2*>(
                    ws + (ci * (K * K) + kh * K + kw) * COT);
                unsigned long long vv[WT];
#pragma unroll
                for (int k = 0; k < WT; k++) {
                    int wi = wcol[k] * ST - PD + kw;
                    float v = ((unsigned)wi < (unsigned)WIN) ? rp[wi] : 0.0f;
                    vv[k] = pk2(v);
                }
#pragma unroll
                for (int j = 0; j < COT / 4; j++) {
                    ulonglong2 w2 = wv[j];
#pragma unroll
                    for (int k = 0; k < WT; k++) {
                        fma2(acc[k][2 * j], vv[k], w2.x);
                        fma2(acc[k][2 * j + 1], vv[k], w2.y);
                    }
                }
            }
        }
    }

    size_t obase = ((size_t)b * CO + cob) * HOUT * WOUT + (size_t)h * WOUT;
#pragma unroll
    for (int k = 0; k < WT; k++)
#pragma unroll
        for (int j = 0; j < COT / 2; j++) {
            float2 r = up2(acc[k][j]);
            float v0 = r.x > 0.0f ? r.x : 0.0f;
            float v1 = r.y > 0.0f ? r.y : 0.0f;
            out[obase + (size_t)(2 * j) * HOUT * WOUT + wcol[k]] = v0;
            out[obase + (size_t)(2 * j + 1) * HOUT * WOUT + wcol[k]] = v1;
        }
}

// ---------------- stride-2 deconv + relu, parity-decomposed, f32x2 ----------------
// blockIdx.z = parity (ph*2+pw). Per parity: dense 2x2-tap conv on H'xW' = HIN x WIN grid.
template<int CI, int CO, int COT, int WT, int HIN, int WIN>
__global__ void deconv_f2_k(const float* __restrict__ in, const float* __restrict__ wp,
                            const float* __restrict__ bias, float* __restrict__ out) {
    constexpr int HOUT = 2 * HIN, WOUT = 2 * WIN;
    extern __shared__ float ws[];                   // [CI*4][COT]
    const int p = blockIdx.z;
    const int ph = p >> 1, pw = p & 1;
    const int cob = blockIdx.y * COT;
    for (int i = threadIdx.x; i < CI * 4 * COT; i += 256) {
        int r = i / COT, c = i % COT;
        ws[i] = wp[(p * CI * 4 + r) * CO + cob + c];
    }
    __syncthreads();

    const int warp = threadIdx.x >> 5, lane = threadIdx.x & 31;
    const int SPR = WIN / (32 * WT);
    int seg = blockIdx.x * 8 + warp;
    int s   = seg % SPR;
    int row = seg / SPR;
    int h   = row % HIN;
    int b   = row / HIN;

    int wcol[WT];
#pragma unroll
    for (int k = 0; k < WT; k++) wcol[k] = s * 32 * WT + lane + 32 * k;

    unsigned long long acc[WT][COT / 2];
#pragma unroll
    for (int k = 0; k < WT; k++)
#pragma unroll
        for (int j = 0; j < COT / 2; j++)
            acc[k][j] = pk(bias[cob + 2 * j], bias[cob + 2 * j + 1]);

    const float* inb = in + (size_t)b * CI * HIN * WIN;
#pragma unroll 2
    for (int ci = 0; ci < CI; ci++) {
        const float* inp = inb + (size_t)ci * HIN * WIN;
#pragma unroll
        for (int a = 0; a < 2; a++) {
            int hi = h + (ph ? a : -a);
            if ((unsigned)hi >= (unsigned)HIN) continue;     // uniform per warp
            const float* rp = inp + hi * WIN;
#pragma unroll
            for (int bt = 0; bt < 2; bt++) {
                const ulonglong2* wv = reinterpret_cast<const ulonglong2*>(
                    ws + (ci * 4 + a * 2 + bt) * COT);
                unsigned long long vv[WT];
#pragma unroll
                for (int k = 0; k < WT; k++) {
                    int wi = wcol[k] + (pw ? bt : -bt);
                    float v = ((unsigned)wi < (unsigned)WIN) ? rp[wi] : 0.0f;
                    vv[k] = pk2(v);
                }
#pragma unroll
                for (int j = 0; j < COT / 4; j++) {
                    ulonglong2 w2 = wv[j];
#pragma unroll
                    for (int k = 0; k < WT; k++) {
                        fma2(acc[k][2 * j], vv[k], w2.x);
                        fma2(acc[k][2 * j + 1], vv[k], w2.y);
                    }
                }
            }
        }
    }

    int ho = 2 * h + ph;
    size_t obase = ((size_t)b * CO + cob) * HOUT * WOUT + (size_t)ho * WOUT;
#pragma unroll
    for (int k = 0; k < WT; k++) {
        int wo = 2 * wcol[k] + pw;
#pragma unroll
        for (int j = 0; j < COT / 2; j++) {
            float2 r = up2(acc[k][j]);
            float v0 = r.x > 0.0f ? r.x : 0.0f;
            float v1 = r.y > 0.0f ? r.y : 0.0f;
            out[obase + (size_t)(2 * j) * HOUT * WOUT + wo] = v0;
            out[obase + (size_t)(2 * j + 1) * HOUT * WOUT + wo] = v1;
        }
    }
}

// ---------------- small-CO stride-1 conv + sigmoid (dc3) ----------------
template<int CI, int K, int CO, int WT, int HIN, int WIN, int PD>
__global__ void conv_sig_k(const float* __restrict__ in, const float* __restrict__ wt,
                           const float* __restrict__ bias, float* __restrict__ out) {
    constexpr int HOUT = HIN, WOUT = WIN;
    extern __shared__ float ws[];                   // [CI*K*K][CO]
    for (int i = threadIdx.x; i < CI * K * K * CO; i += 256) ws[i] = wt[i];
    __syncthreads();

    const int warp = threadIdx.x >> 5, lane = threadIdx.x & 31;
    const int SPR = WOUT / (32 * WT);
    int seg = blockIdx.x * 8 + warp;
    int s   = seg % SPR;
    int row = seg / SPR;
    int h   = row % HOUT;
    int b   = row / HOUT;

    int wcol[WT];
#pragma unroll
    for (int k = 0; k < WT; k++) wcol[k] = s * 32 * WT + lane + 32 * k;

    float acc[WT][CO];
#pragma unroll
    for (int k = 0; k < WT; k++)
#pragma unroll
        for (int c = 0; c < CO; c++) acc[k][c] = bias[c];

    const float* inb = in + (size_t)b * CI * HIN * WIN;
#pragma unroll 2
    for (int ci = 0; ci < CI; ci++) {
        const float* inp = inb + (size_t)ci * HIN * WIN;
#pragma unroll
        for (int kh = 0; kh < K; kh++) {
            int hi = h - PD + kh;
            if ((unsigned)hi >= (unsigned)HIN) continue;
            const float* rp = inp + hi * WIN;
#pragma unroll
            for (int kw = 0; kw < K; kw++) {
                const float* wr = ws + (ci * (K * K) + kh * K + kw) * CO;
                float v[WT];
#pragma unroll
                for (int k = 0; k < WT; k++) {
                    int wi = wcol[k] - PD + kw;
                    v[k] = ((unsigned)wi < (unsigned)WIN) ? rp[wi] : 0.0f;
                }
#pragma unroll
                for (int c = 0; c < CO; c++) {
                    float w = wr[c];
#pragma unroll
                    for (int k = 0; k < WT; k++) acc[k][c] += v[k] * w;
                }
            }
        }
    }

    size_t obase = (size_t)b * CO * HOUT * WOUT + (size_t)h * WOUT;
#pragma unroll
    for (int k = 0; k < WT; k++)
#pragma unroll
        for (int c = 0; c < CO; c++) {
            float v = 1.0f / (1.0f + expf(-acc[k][c]));
            out[obase + (size_t)c * HOUT * WOUT + wcol[k]] = v;
        }
}

// ---------------- vector quantize (z NCHW) -> indices + loss ----------------
__global__ void vq_k(const float* __restrict__ emb, const float* __restrict__ z,
                     int* __restrict__ idx) {
    extern __shared__ float sm[];
    float* se = sm;              // 512*64 codebook
    float* sn = sm + 512 * 64;   // 512 norms
    for (int i = threadIdx.x; i < 512 * 64; i += blockDim.x) se[i] = emb[i];
    __syncthreads();
    for (int k = threadIdx.x; k < 512; k += blockDim.x) {
        float s = 0.0f;
#pragma unroll
        for (int j = 0; j < 64; j++) { float e = se[k * 64 + j]; s += e * e; }
        sn[k] = s;
    }
    __syncthreads();

    int n = blockIdx.x * blockDim.x + threadIdx.x;   // pixel id
    int b  = n >> 12;
    int hw = n & 4095;
    const float* zp = z + (size_t)b * 262144 + hw;   // NCHW: stride 4096 per channel
    float zr[64];
#pragma unroll
    for (int j = 0; j < 64; j++) zr[j] = zp[(size_t)j * 4096];

    float best = 3.4e38f;
    int bi = 0;
    for (int k = 0; k < 512; k++) {
        const float4* e4 = reinterpret_cast<const float4*>(se + k * 64);
        float dot = 0.0f;
#pragma unroll
        for (int j = 0; j < 16; j++) {
            float4 e = e4[j];
            dot += zr[4 * j]     * e.x;
            dot += zr[4 * j + 1] * e.y;
            dot += zr[4 * j + 2] * e.z;
            dot += zr[4 * j + 3] * e.w;
        }
        float d = sn[k] - 2.0f * dot;     // + ||z||^2 is constant per row
        if (d < best) { best = d; bi = k; }
    }

    idx[n] = bi;
    float ls = 0.0f;
#pragma unroll
    for (int j = 0; j < 64; j++) {
        float df = se[bi * 64 + j] - zr[j];
        ls += df * df;
    }
#pragma unroll
    for (int o = 16; o > 0; o >>= 1) ls += __shfl_xor_sync(0xffffffffu, ls, o);
    if ((threadIdx.x & 31) == 0) atomicAdd(&g_loss, ls);
}

// materialize q in NCHW, coalesced
__global__ void gather_q_k(const float* __restrict__ emb, const int* __restrict__ idx,
                           float* __restrict__ q) {
    int i = blockIdx.x * blockDim.x + threadIdx.x;   // over 32*64*4096
    int hw = i & 4095;
    int t  = i >> 12;
    int c  = t & 63;
    int b  = t >> 6;
    q[i] = emb[idx[(b << 12) + hw] * 64 + c];
}

// ---------------- host ----------------
static float* sym_addr(const void* sym) {
    void* p = nullptr;
    cudaGetSymbolAddress(&p, sym);
    return (float*)p;
}

extern "C" void kernel_launch(void* const* d_in, const int* in_sizes, int n_in,
                              void* d_out, int out_size) {
    const float* x   = (const float*)d_in[0];
    const float* w1  = (const float*)d_in[1];
    const float* b1  = (const float*)d_in[2];
    const float* w2  = (const float*)d_in[3];
    const float* b2  = (const float*)d_in[4];
    const float* w3  = (const float*)d_in[5];
    const float* b3  = (const float*)d_in[6];
    const float* emb = (const float*)d_in[7];
    const float* dw1 = (const float*)d_in[8];
    const float* db1 = (const float*)d_in[9];
    const float* dw2 = (const float*)d_in[10];
    const float* db2 = (const float*)d_in[11];
    const float* dw3 = (const float*)d_in[12];
    const float* db3 = (const float*)d_in[13];
    float* out = (float*)d_out;

    float* h1   = sym_addr(g_h1);
    float* h2   = sym_addr(g_h2);
    float* z    = sym_addr(g_z);
    float* q    = sym_addr(g_q);
    float* d1   = sym_addr(g_d1);
    float* d2   = sym_addr(g_d2);
    float* wt1  = sym_addr(g_wt1);
    float* wt2  = sym_addr(g_wt2);
    float* wt3  = sym_addr(g_wt3);
    float* pw1  = sym_addr(g_pw1);
    float* pw2  = sym_addr(g_pw2);
    float* wt3d = sym_addr(g_wt3d);
    int*   idx  = (int*)sym_addr(g_idx);

    auto c1  = conv_f2_k<3, 4, 64, 32, 2, 256, 256, 128, 128, 2, 1>;
    auto c2  = conv_f2_k<64, 4, 128, 32, 2, 128, 128, 64, 64, 2, 1>;
    auto c3  = conv_f2_k<128, 3, 64, 32, 2, 64, 64, 64, 64, 1, 1>;
    auto dc1 = deconv_f2_k<64, 128, 32, 2, 64, 64>;
    auto dc2 = deconv_f2_k<128, 64, 32, 2, 128, 128>;
    auto dc3 = conv_sig_k<64, 3, 3, 4, 256, 256, 1>;

    cudaFuncSetAttribute(c2,  cudaFuncAttributeMaxDynamicSharedMemorySize, 64 * 16 * 32 * 4);
    cudaFuncSetAttribute(c3,  cudaFuncAttributeMaxDynamicSharedMemorySize, 128 * 9 * 32 * 4);
    cudaFuncSetAttribute(dc2, cudaFuncAttributeMaxDynamicSharedMemorySize, 128 * 4 * 32 * 4);
    cudaFuncSetAttribute(vq_k, cudaFuncAttributeMaxDynamicSharedMemorySize, (512 * 64 + 512) * 4);

    // repack weights
    repack_conv<<<(64 * 3 * 16 + 255) / 256, 256>>>(w1, wt1, 64, 3, 16);
    repack_conv<<<(128 * 64 * 16 + 255) / 256, 256>>>(w2, wt2, 128, 64, 16);
    repack_conv<<<(64 * 128 * 9 + 255) / 256, 256>>>(w3, wt3, 64, 128, 9);
    repack_par<<<(4 * 64 * 4 * 128 + 255) / 256, 256>>>(dw1, pw1, 64, 128);
    repack_par<<<(4 * 128 * 4 * 64 + 255) / 256, 256>>>(dw2, pw2, 128, 64);
    repack_deconv_flip<<<(64 * 3 * 9 + 255) / 256, 256>>>(dw3, wt3d, 3, 64, 3);
    zero_loss_k<<<1, 1>>>();

    // encoder
    c1<<<dim3(1024, 2), 256, 3 * 16 * 32 * 4>>>(x, wt1, b1, h1);
    c2<<<dim3(256, 4), 256, 64 * 16 * 32 * 4>>>(h1, wt2, b2, h2);
    c3<<<dim3(256, 2), 256, 128 * 9 * 32 * 4>>>(h2, wt3, b3, z);

    // vector quantize
    vq_k<<<512, 256, (512 * 64 + 512) * 4>>>(emb, z, idx);
    gather_q_k<<<(32 * 64 * 4096) / 256, 256>>>(emb, idx, q);

    // decoder
    dc1<<<dim3(256, 4, 4), 256, 64 * 4 * 32 * 4>>>(q, pw1, db1, d1);
    dc2<<<dim3(1024, 2, 4), 256, 128 * 4 * 32 * 4>>>(d1, pw2, db2, d2);
    dc3<<<dim3(2048, 1), 256, 64 * 9 * 3 * 4>>>(d2, wt3d, db3, out);

    finalize_k<<<1, 1>>>(out, out_size - 1);
}

// round 4
// speedup vs baseline: 6.4999x; 1.3814x over previous
#include <cuda_runtime.h>
#include <math.h>

// ---------------- scratch (device globals: allocation-free rule) ----------------
__device__ float g_h1[32u * 64 * 128 * 128];   // after conv1+relu   (NCHW)
__device__ float g_h2[32u * 128 * 64 * 64];    // after conv2+relu   (NCHW)
__device__ float g_z [32u * 64 * 64 * 64];     // after conv3+relu   (NCHW)
__device__ float g_q [32u * 64 * 64 * 64];     // quantized          (NCHW)
__device__ float g_d1[32u * 128 * 128 * 128];  // after deconv1+relu (NCHW)
__device__ float g_d2[32u * 64 * 256 * 256];   // after deconv2+relu (NCHW)
__device__ int   g_idx[32 * 64 * 64];

// repacked weights
__device__ float  g_wt1 [64 * 3 * 16];          // [(ci*16+t)*64+co] (c1, FFMA2 path)
__device__ float  g_wt3 [64 * 128 * 9];         // c3
__device__ float  g_wt3d[3 * 64 * 9];           // flipped dc3 -> plain conv
__device__ float2 g_pw1p[4 * 32 * 4 * 128];     // dc1 mma pairs [p][cp][tap][co]
__device__ float2 g_pw2p[4 * 64 * 4 * 64];      // dc2 mma pairs
__device__ float2 g_cw2p[64 * 8 * 128];         // c2  mma pairs [ci][th*4+kw][co]

__device__ float g_loss;

// ---------------- helpers ----------------
__device__ __forceinline__ float cvt_tf32(float x) {
    asm("cvt.rna.tf32.f32 %0, %0;" : "+f"(x));
    return x;
}
__device__ __forceinline__ unsigned long long pk2(float x) {
    unsigned long long r;
    asm("mov.b64 %0, {%1, %1};" : "=l"(r) : "f"(x));
    return r;
}
__device__ __forceinline__ unsigned long long pk(float x, float y) {
    unsigned long long r;
    asm("mov.b64 %0, {%1, %2};" : "=l"(r) : "f"(x), "f"(y));
    return r;
}
__device__ __forceinline__ void fma2(unsigned long long& d,
                                     unsigned long long a, unsigned long long b) {
    asm("fma.rn.f32x2 %0, %1, %2, %0;" : "+l"(d) : "l"(a), "l"(b));
}
__device__ __forceinline__ float2 up2(unsigned long long v) {
    float2 f;
    asm("mov.b64 {%0, %1}, %2;" : "=f"(f.x), "=f"(f.y) : "l"(v));
    return f;
}
__device__ __forceinline__ void mma_tf32(float* c, unsigned a0, unsigned a1,
                                         unsigned a2, unsigned a3,
                                         unsigned b0, unsigned b1) {
    asm volatile(
        "mma.sync.aligned.m16n8k8.row.col.f32.tf32.tf32.f32 "
        "{%0,%1,%2,%3}, {%4,%5,%6,%7}, {%8,%9}, {%0,%1,%2,%3};"
        : "+f"(c[0]), "+f"(c[1]), "+f"(c[2]), "+f"(c[3])
        : "r"(a0), "r"(a1), "r"(a2), "r"(a3), "r"(b0), "r"(b1));
}

// ---------------- weight repack ----------------
__global__ void repack_conv(const float* __restrict__ w, float* __restrict__ wt,
                            int Co, int Ci, int KK) {
    int i = blockIdx.x * blockDim.x + threadIdx.x;
    if (i >= Co * Ci * KK) return;
    int co = i / (Ci * KK);
    int r  = i % (Ci * KK);
    wt[r * Co + co] = w[i];
}
__global__ void repack_deconv_flip(const float* __restrict__ w, float* __restrict__ wt,
                                   int Co, int Ci, int K) {
    int KK = K * K;
    int i = blockIdx.x * blockDim.x + threadIdx.x;
    if (i >= Ci * Co * KK) return;
    int ci = i / (Co * KK);
    int r  = i % (Co * KK);
    int co = r / KK;
    int t  = r % KK;
    int kh = t / K, kw = t % K;
    int tf = (K - 1 - kh) * K + (K - 1 - kw);
    wt[(ci * KK + tf) * Co + co] = w[i];
}
// stride-2 deconv, parity + ci-pair packing for mma b-frags.
// pwp[((p*(CI/2)+cp)*4 + tap)*CO + co] = (w[2cp], w[2cp+1]) at (kh(p,a), kw(p,bt)), tf32.
__global__ void repack_par_pair(const float* __restrict__ w, float2* __restrict__ pwp,
                                int CI, int CO) {
    int i = blockIdx.x * blockDim.x + threadIdx.x;
    int total = 4 * (CI / 2) * 4 * CO;
    if (i >= total) return;
    int p  = i / ((CI / 2) * 4 * CO);
    int r  = i % ((CI / 2) * 4 * CO);
    int cp = r / (4 * CO);
    int r2 = r % (4 * CO);
    int tap = r2 / CO;
    int co  = r2 % CO;
    int a = tap >> 1, bt = tap & 1;
    int ph = p >> 1, pw = p & 1;
    int kh = ph ? (a ? 0 : 2) : (a ? 3 : 1);
    int kw = pw ? (bt ? 0 : 2) : (bt ? 3 : 1);
    float v0 = w[(((2 * cp) * CO + co) * 4 + kh) * 4 + kw];
    float v1 = w[(((2 * cp + 1) * CO + co) * 4 + kh) * 4 + kw];
    pwp[i] = make_float2(cvt_tf32(v0), cvt_tf32(v1));
}
// conv2 (4x4 s2) kh-pair packing: cw2[(ci*8 + th*4 + kw)*CO + co] = (w[2th][kw], w[2th+1][kw])
__global__ void repack_c2_pair(const float* __restrict__ w, float2* __restrict__ cw2,
                               int CI, int CO) {
    int i = blockIdx.x * blockDim.x + threadIdx.x;
    int total = CI * 8 * CO;
    if (i >= total) return;
    int ci = i / (8 * CO);
    int r  = i % (8 * CO);
    int pi = r / CO;
    int co = r % CO;
    int th = pi >> 2, kw = pi & 3;
    float v0 = w[((co * CI + ci) * 4 + 2 * th) * 4 + kw];
    float v1 = w[((co * CI + ci) * 4 + 2 * th + 1) * 4 + kw];
    cw2[i] = make_float2(cvt_tf32(v0), cvt_tf32(v1));
}

__global__ void zero_loss_k() { g_loss = 0.0f; }
__global__ void finalize_k(float* __restrict__ out, int loss_idx) {
    out[loss_idx] = 1.25f * g_loss * (1.0f / 8388608.0f);
}

// ================= MMA implicit-GEMM: parity-decomposed stride-2 deconv =================
// blockIdx.z = parity. CTA: 256 thr = 8 warps; output tile M=128 spatial (MH rows x MW) x N=CO.
template<int CI, int CO, int MH, int MW, int HIN, int WIN, int KC>
__global__ void deconv_mma_k(const float* __restrict__ in, const float2* __restrict__ wp,
                             const float* __restrict__ bias, float* __restrict__ out) {
    constexpr int R = MH + 1, MWP = MW + 2;
    constexpr int NT = CO / 8;
    constexpr int ASZ = KC * R * MWP;        // floats
    constexpr int BSZ = (KC / 2) * 4 * CO;   // float2
    constexpr int HOUT = 2 * HIN, WOUT = 2 * WIN;
    extern __shared__ float sm[];
    float*  sA = sm;
    float2* sB = (float2*)(sm + ASZ);        // ASZ even -> 8B aligned

    const int p  = blockIdx.z, ph = p >> 1, pw = p & 1;
    const int tiles_h = HIN / MH;
    const int h0 = (blockIdx.x % tiles_h) * MH;
    const int b  = blockIdx.x / tiles_h;
    const int warp = threadIdx.x >> 5, lane = threadIdx.x & 31;
    const int tap = lane & 3;
    const int a = tap >> 1, bt = tap & 1;
    const int roff = ph ? a : 1 - a;
    const int coff = pw ? bt : 1 - bt;
    const int mbase = warp * 16;
    const int mr = mbase / MW;               // constant per warp
    const int mw_lo = (mbase % MW) + (lane >> 2);
    const int aoff0 = (mr + roff) * MWP + mw_lo + coff;

    float acc[NT][4];
#pragma unroll
    for (int nt = 0; nt < NT; nt++) {
        float b0v = bias[nt * 8 + 2 * (lane & 3)];
        float b1v = bias[nt * 8 + 2 * (lane & 3) + 1];
        acc[nt][0] = b0v; acc[nt][1] = b1v; acc[nt][2] = b0v; acc[nt][3] = b1v;
    }

    const float* inb = in + (size_t)b * CI * HIN * WIN;
    for (int ci0 = 0; ci0 < CI; ci0 += KC) {
        __syncthreads();
        // stage A (input halo tile, tf32-rounded)
        for (int i = threadIdx.x; i < ASZ; i += 256) {
            int ci_l = i / (R * MWP);
            int rem  = i % (R * MWP);
            int r = rem / MWP, c = rem % MWP;
            int gr = h0 + r - (ph ? 0 : 1);
            int gc = c - (pw ? 0 : 1);
            float v = 0.0f;
            if ((unsigned)gr < (unsigned)HIN && (unsigned)gc < (unsigned)WIN)
                v = inb[(size_t)(ci0 + ci_l) * HIN * WIN + gr * WIN + gc];
            sA[i] = cvt_tf32(v);
        }
        // stage B (prepacked, contiguous)
        const float2* src = wp + ((size_t)(p * (CI / 2) + ci0 / 2) * 4) * CO;
        for (int i = threadIdx.x; i < BSZ; i += 256) sB[i] = src[i];
        __syncthreads();

#pragma unroll
        for (int s = 0; s < KC / 2; s++) {
            const float* pa = sA + 2 * s * R * MWP + aoff0;
            unsigned a0 = __float_as_uint(pa[0]);
            unsigned a1 = __float_as_uint(pa[8]);
            unsigned a2 = __float_as_uint(pa[R * MWP]);
            unsigned a3 = __float_as_uint(pa[R * MWP + 8]);
            const float2* pb = sB + (s * 4 + tap) * CO + (lane >> 2);
#pragma unroll
            for (int nt = 0; nt < NT; nt++) {
                float2 bb = pb[nt * 8];
                mma_tf32(acc[nt], a0, a1, a2, a3,
                         __float_as_uint(bb.x), __float_as_uint(bb.y));
            }
        }
    }

    // store (parity upsample) + relu
    const int ho = 2 * (h0 + mr) + ph;
    const int wo_lo = 2 * mw_lo + pw;
#pragma unroll
    for (int nt = 0; nt < NT; nt++) {
        int n0 = nt * 8 + 2 * (lane & 3);
#pragma unroll
        for (int j = 0; j < 4; j++) {
            int n  = n0 + (j & 1);
            int wo = wo_lo + ((j >> 1) ? 16 : 0);
            float v = acc[nt][j];
            v = v > 0.0f ? v : 0.0f;
            out[((size_t)(b * CO + n) * HOUT + ho) * WOUT + wo] = v;
        }
    }
}

// ================= MMA implicit-GEMM: conv2 4x4 stride-2 =================
// CTA: 256 thr; tile M=128 (MH=2 rows x MW=64) x N=CO. K = ci*16 taps.
template<int CI, int CO, int HIN, int WIN, int KC>
__global__ void conv2_mma_k(const float* __restrict__ in, const float2* __restrict__ cw,
                            const float* __restrict__ bias, float* __restrict__ out) {
    constexpr int MH = 2, MW = 64;
    constexpr int R = 6, MWP = 2 * MW + 2;   // 130
    constexpr int NT = CO / 8;
    constexpr int ASZ = KC * R * MWP;        // floats
    constexpr int BSZ = KC * 8 * CO;         // float2
    constexpr int HOUT = HIN / 2, WOUT = WIN / 2;
    extern __shared__ float sm[];
    float*  sA = sm;
    float2* sB = (float2*)(sm + ASZ);

    const int tiles_h = HOUT / MH;
    const int h0 = (blockIdx.x % tiles_h) * MH;
    const int b  = blockIdx.x / tiles_h;
    const int warp = threadIdx.x >> 5, lane = threadIdx.x & 31;
    const int kw = lane & 3;
    const int mbase = warp * 16;
    const int mr = mbase / MW;
    const int mw_lo = (mbase % MW) + (lane >> 2);

    float acc[NT][4];
#pragma unroll
    for (int nt = 0; nt < NT; nt++) {
        float b0v = bias[nt * 8 + 2 * (lane & 3)];
        float b1v = bias[nt * 8 + 2 * (lane & 3) + 1];
        acc[nt][0] = b0v; acc[nt][1] = b1v; acc[nt][2] = b0v; acc[nt][3] = b1v;
    }

    const float* inb = in + (size_t)b * CI * HIN * WIN;
    for (int ci0 = 0; ci0 < CI; ci0 += KC) {
        __syncthreads();
        for (int i = threadIdx.x; i < ASZ; i += 256) {
            int ci_l = i / (R * MWP);
            int rem  = i % (R * MWP);
            int r = rem / MWP, c = rem % MWP;
            int gr = 2 * h0 + r - 1;
            int gc = c - 1;
            float v = 0.0f;
            if ((unsigned)gr < (unsigned)HIN && (unsigned)gc < (unsigned)WIN)
                v = inb[(size_t)(ci0 + ci_l) * HIN * WIN + gr * WIN + gc];
            sA[i] = cvt_tf32(v);
        }
        const float2* src = cw + (size_t)ci0 * 8 * CO;
        for (int i = threadIdx.x; i < BSZ; i += 256) sB[i] = src[i];
        __syncthreads();

#pragma unroll
        for (int s = 0; s < 2 * KC; s++) {
            int ci_l = s >> 1, th = s & 1;
            const float* pa = sA + ci_l * R * MWP + (2 * mr + 2 * th) * MWP
                              + 2 * mw_lo + kw;
            unsigned a0 = __float_as_uint(pa[0]);
            unsigned a1 = __float_as_uint(pa[16]);
            unsigned a2 = __float_as_uint(pa[MWP]);
            unsigned a3 = __float_as_uint(pa[MWP + 16]);
            const float2* pb = sB + (ci_l * 8 + th * 4 + kw) * CO + (lane >> 2);
#pragma unroll
            for (int nt = 0; nt < NT; nt++) {
                float2 bb = pb[nt * 8];
                mma_tf32(acc[nt], a0, a1, a2, a3,
                         __float_as_uint(bb.x), __float_as_uint(bb.y));
            }
        }
    }

    const int ho = h0 + mr;
#pragma unroll
    for (int nt = 0; nt < NT; nt++) {
        int n0 = nt * 8 + 2 * (lane & 3);
#pragma unroll
        for (int j = 0; j < 4; j++) {
            int n  = n0 + (j & 1);
            int wo = mw_lo + ((j >> 1) ? 8 : 0);
            float v = acc[nt][j];
            v = v > 0.0f ? v : 0.0f;
            out[((size_t)(b * CO + n) * HOUT + ho) * WOUT + wo] = v;
        }
    }
}

// ---------------- conv + relu, f32x2 (c1, c3) ----------------
template<int CI, int K, int CO, int COT, int WT,
         int HIN, int WIN, int HOUT, int WOUT, int ST, int PD>
__global__ void conv_f2_k(const float* __restrict__ in, const float* __restrict__ wt,
                          const float* __restrict__ bias, float* __restrict__ out) {
    extern __shared__ float ws[];
    const int cob = blockIdx.y * COT;
    const int WROWS = CI * K * K;
    for (int i = threadIdx.x; i < WROWS * COT; i += 256) {
        int r = i / COT, c = i % COT;
        ws[i] = wt[r * CO + cob + c];
    }
    __syncthreads();

    const int warp = threadIdx.x >> 5, lane = threadIdx.x & 31;
    const int SPR = WOUT / (32 * WT);
    int seg = blockIdx.x * 8 + warp;
    int s   = seg % SPR;
    int row = seg / SPR;
    int h   = row % HOUT;
    int b   = row / HOUT;

    int wcol[WT];
#pragma unroll
    for (int k = 0; k < WT; k++) wcol[k] = s * 32 * WT + lane + 32 * k;

    unsigned long long acc[WT][COT / 2];
#pragma unroll
    for (int k = 0; k < WT; k++)
#pragma unroll
        for (int j = 0; j < COT / 2; j++)
            acc[k][j] = pk(bias[cob + 2 * j], bias[cob + 2 * j + 1]);

    const float* inb = in + (size_t)b * CI * HIN * WIN;
#pragma unroll 2
    for (int ci = 0; ci < CI; ci++) {
        const float* inp = inb + (size_t)ci * HIN * WIN;
#pragma unroll
        for (int kh = 0; kh < K; kh++) {
            int hi = h * ST - PD + kh;
            if ((unsigned)hi >= (unsigned)HIN) continue;
            const float* rp = inp + hi * WIN;
#pragma unroll
            for (int kw = 0; kw < K; kw++) {
                const ulonglong2* wv = reinterpret_cast<const ulonglong2*>(
                    ws + (ci * (K * K) + kh * K + kw) * COT);
                unsigned long long vv[WT];
#pragma unroll
                for (int k = 0; k < WT; k++) {
                    int wi = wcol[k] * ST - PD + kw;
                    float v = ((unsigned)wi < (unsigned)WIN) ? rp[wi] : 0.0f;
                    vv[k] = pk2(v);
                }
#pragma unroll
                for (int j = 0; j < COT / 4; j++) {
                    ulonglong2 w2 = wv[j];
#pragma unroll
                    for (int k = 0; k < WT; k++) {
                        fma2(acc[k][2 * j], vv[k], w2.x);
                        fma2(acc[k][2 * j + 1], vv[k], w2.y);
                    }
                }
            }
        }
    }

    size_t obase = ((size_t)b * CO + cob) * HOUT * WOUT + (size_t)h * WOUT;
#pragma unroll
    for (int k = 0; k < WT; k++)
#pragma unroll
        for (int j = 0; j < COT / 2; j++) {
            float2 r = up2(acc[k][j]);
            float v0 = r.x > 0.0f ? r.x : 0.0f;
            float v1 = r.y > 0.0f ? r.y : 0.0f;
            out[obase + (size_t)(2 * j) * HOUT * WOUT + wcol[k]] = v0;
            out[obase + (size_t)(2 * j + 1) * HOUT * WOUT + wcol[k]] = v1;
        }
}

// ---------------- small-CO stride-1 conv + sigmoid (dc3) ----------------
template<int CI, int K, int CO, int WT, int HIN, int WIN, int PD>
__global__ void conv_sig_k(const float* __restrict__ in, const float* __restrict__ wt,
                           const float* __restrict__ bias, float* __restrict__ out) {
    constexpr int HOUT = HIN, WOUT = WIN;
    extern __shared__ float ws[];
    for (int i = threadIdx.x; i < CI * K * K * CO; i += 256) ws[i] = wt[i];
    __syncthreads();

    const int warp = threadIdx.x >> 5, lane = threadIdx.x & 31;
    const int SPR = WOUT / (32 * WT);
    int seg = blockIdx.x * 8 + warp;
    int s   = seg % SPR;
    int row = seg / SPR;
    int h   = row % HOUT;
    int b   = row / HOUT;

    int wcol[WT];
#pragma unroll
    for (int k = 0; k < WT; k++) wcol[k] = s * 32 * WT + lane + 32 * k;

    float acc[WT][CO];
#pragma unroll
    for (int k = 0; k < WT; k++)
#pragma unroll
        for (int c = 0; c < CO; c++) acc[k][c] = bias[c];

    const float* inb = in + (size_t)b * CI * HIN * WIN;
#pragma unroll 2
    for (int ci = 0; ci < CI; ci++) {
        const float* inp = inb + (size_t)ci * HIN * WIN;
#pragma unroll
        for (int kh = 0; kh < K; kh++) {
            int hi = h - PD + kh;
            if ((unsigned)hi >= (unsigned)HIN) continue;
            const float* rp = inp + hi * WIN;
#pragma unroll
            for (int kw = 0; kw < K; kw++) {
                const float* wr = ws + (ci * (K * K) + kh * K + kw) * CO;
                float v[WT];
#pragma unroll
                for (int k = 0; k < WT; k++) {
                    int wi = wcol[k] - PD + kw;
                    v[k] = ((unsigned)wi < (unsigned)WIN) ? rp[wi] : 0.0f;
                }
#pragma unroll
                for (int c = 0; c < CO; c++) {
                    float w = wr[c];
#pragma unroll
                    for (int k = 0; k < WT; k++) acc[k][c] += v[k] * w;
                }
            }
        }
    }

    size_t obase = (size_t)b * CO * HOUT * WOUT + (size_t)h * WOUT;
#pragma unroll
    for (int k = 0; k < WT; k++)
#pragma unroll
        for (int c = 0; c < CO; c++) {
            float v = 1.0f / (1.0f + expf(-acc[k][c]));
            out[obase + (size_t)c * HOUT * WOUT + wcol[k]] = v;
        }
}

// ---------------- vector quantize (z NCHW) -> indices + loss ----------------
__global__ void vq_k(const float* __restrict__ emb, const float* __restrict__ z,
                     int* __restrict__ idx) {
    extern __shared__ float sm[];
    float* se = sm;
    float* sn = sm + 512 * 64;
    for (int i = threadIdx.x; i < 512 * 64; i += blockDim.x) se[i] = emb[i];
    __syncthreads();
    for (int k = threadIdx.x; k < 512; k += blockDim.x) {
        float s = 0.0f;
#pragma unroll
        for (int j = 0; j < 64; j++) { float e = se[k * 64 + j]; s += e * e; }
        sn[k] = s;
    }
    __syncthreads();

    int n = blockIdx.x * blockDim.x + threadIdx.x;
    int b  = n >> 12;
    int hw = n & 4095;
    const float* zp = z + (size_t)b * 262144 + hw;
    float zr[64];
#pragma unroll
    for (int j = 0; j < 64; j++) zr[j] = zp[(size_t)j * 4096];

    float best = 3.4e38f;
    int bi = 0;
    for (int k = 0; k < 512; k++) {
        const float4* e4 = reinterpret_cast<const float4*>(se + k * 64);
        float dot = 0.0f;
#pragma unroll
        for (int j = 0; j < 16; j++) {
            float4 e = e4[j];
            dot += zr[4 * j]     * e.x;
            dot += zr[4 * j + 1] * e.y;
            dot += zr[4 * j + 2] * e.z;
            dot += zr[4 * j + 3] * e.w;
        }
        float d = sn[k] - 2.0f * dot;
        if (d < best) { best = d; bi = k; }
    }

    idx[n] = bi;
    float ls = 0.0f;
#pragma unroll
    for (int j = 0; j < 64; j++) {
        float df = se[bi * 64 + j] - zr[j];
        ls += df * df;
    }
#pragma unroll
    for (int o = 16; o > 0; o >>= 1) ls += __shfl_xor_sync(0xffffffffu, ls, o);
    if ((threadIdx.x & 31) == 0) atomicAdd(&g_loss, ls);
}

__global__ void gather_q_k(const float* __restrict__ emb, const int* __restrict__ idx,
                           float* __restrict__ q) {
    int i = blockIdx.x * blockDim.x + threadIdx.x;
    int hw = i & 4095;
    int t  = i >> 12;
    int c  = t & 63;
    int b  = t >> 6;
    q[i] = emb[idx[(b << 12) + hw] * 64 + c];
}

// ---------------- host ----------------
static float* sym_addr(const void* sym) {
    void* p = nullptr;
    cudaGetSymbolAddress(&p, sym);
    return (float*)p;
}

extern "C" void kernel_launch(void* const* d_in, const int* in_sizes, int n_in,
                              void* d_out, int out_size) {
    const float* x   = (const float*)d_in[0];
    const float* w1  = (const float*)d_in[1];
    const float* b1  = (const float*)d_in[2];
    const float* w2  = (const float*)d_in[3];
    const float* b2  = (const float*)d_in[4];
    const float* w3  = (const float*)d_in[5];
    const float* b3  = (const float*)d_in[6];
    const float* emb = (const float*)d_in[7];
    const float* dw1 = (const float*)d_in[8];
    const float* db1 = (const float*)d_in[9];
    const float* dw2 = (const float*)d_in[10];
    const float* db2 = (const float*)d_in[11];
    const float* dw3 = (const float*)d_in[12];
    const float* db3 = (const float*)d_in[13];
    float* out = (float*)d_out;

    float*  h1   = sym_addr(g_h1);
    float*  h2   = sym_addr(g_h2);
    float*  z    = sym_addr(g_z);
    float*  q    = sym_addr(g_q);
    float*  d1   = sym_addr(g_d1);
    float*  d2   = sym_addr(g_d2);
    float*  wt1  = sym_addr(g_wt1);
    float*  wt3  = sym_addr(g_wt3);
    float*  wt3d = sym_addr(g_wt3d);
    float2* pw1p = (float2*)sym_addr(g_pw1p);
    float2* pw2p = (float2*)sym_addr(g_pw2p);
    float2* cw2p = (float2*)sym_addr(g_cw2p);
    int*    idx  = (int*)sym_addr(g_idx);

    auto c1  = conv_f2_k<3, 4, 64, 32, 2, 256, 256, 128, 128, 2, 1>;
    auto c2m = conv2_mma_k<64, 128, 128, 128, 4>;
    auto c3  = conv_f2_k<128, 3, 64, 32, 2, 64, 64, 64, 64, 1, 1>;
    auto dc1 = deconv_mma_k<64, 128, 2, 64, 64, 64, 8>;
    auto dc2 = deconv_mma_k<128, 64, 1, 128, 128, 128, 8>;
    auto dc3 = conv_sig_k<64, 3, 3, 4, 256, 256, 1>;

    cudaFuncSetAttribute(c3,  cudaFuncAttributeMaxDynamicSharedMemorySize, 128 * 9 * 32 * 4);
    cudaFuncSetAttribute(c2m, cudaFuncAttributeMaxDynamicSharedMemorySize, 46000);
    cudaFuncSetAttribute(vq_k, cudaFuncAttributeMaxDynamicSharedMemorySize, (512 * 64 + 512) * 4);

    // repack weights
    repack_conv<<<(64 * 3 * 16 + 255) / 256, 256>>>(w1, wt1, 64, 3, 16);
    repack_c2_pair<<<(64 * 8 * 128 + 255) / 256, 256>>>(w2, cw2p, 64, 128);
    repack_conv<<<(64 * 128 * 9 + 255) / 256, 256>>>(w3, wt3, 64, 128, 9);
    repack_par_pair<<<(4 * 32 * 4 * 128 + 255) / 256, 256>>>(dw1, pw1p, 64, 128);
    repack_par_pair<<<(4 * 64 * 4 * 64 + 255) / 256, 256>>>(dw2, pw2p, 128, 64);
    repack_deconv_flip<<<(64 * 3 * 9 + 255) / 256, 256>>>(dw3, wt3d, 3, 64, 3);
    zero_loss_k<<<1, 1>>>();

    // encoder
    c1<<<dim3(1024, 2), 256, 3 * 16 * 32 * 4>>>(x, wt1, b1, h1);
    {   // c2 mma: A = 4*6*130 fl, B = 4*8*128 f2
        int smem = 4 * 6 * 130 * 4 + 4 * 8 * 128 * 8;
        c2m<<<dim3(32 * 32), 256, smem>>>(h1, cw2p, b2, h2);
    }
    c3<<<dim3(256, 2), 256, 128 * 9 * 32 * 4>>>(h2, wt3, b3, z);

    // vector quantize
    vq_k<<<512, 256, (512 * 64 + 512) * 4>>>(emb, z, idx);
    gather_q_k<<<(32 * 64 * 4096) / 256, 256>>>(emb, idx, q);

    // decoder
    {   // dc1: A = 8*3*66 fl, B = 4*4*128 f2
        int smem = 8 * 3 * 66 * 4 + 4 * 4 * 128 * 8;
        dc1<<<dim3(32 * 32, 1, 4), 256, smem>>>(q, pw1p, db1, d1);
    }
    {   // dc2: A = 8*2*130 fl, B = 4*4*64 f2
        int smem = 8 * 2 * 130 * 4 + 4 * 4 * 64 * 8;
        dc2<<<dim3(32 * 128, 1, 4), 256, smem>>>(d1, pw2p, db2, d2);
    }
    dc3<<<dim3(2048, 1), 256, 64 * 9 * 3 * 4>>>(d2, wt3d, db3, out);

    finalize_k<<<1, 1>>>(out, out_size - 1);
}

// round 5
// speedup vs baseline: 11.7836x; 1.8129x over previous
#include <cuda_runtime.h>
#include <math.h>

// ---------------- scratch (device globals: allocation-free rule) ----------------
__device__ float g_h1[32u * 64 * 128 * 128];   // after conv1+relu   (NCHW)
__device__ float g_h2[32u * 128 * 64 * 64];    // after conv2+relu   (NCHW)
__device__ float g_z [32u * 64 * 64 * 64];     // after conv3+relu   (NCHW)
__device__ float g_q [32u * 64 * 64 * 64];     // quantized          (NCHW)
__device__ float g_d1[32u * 128 * 128 * 128];  // after deconv1+relu (NCHW)
__device__ float g_d2[32u * 64 * 256 * 256];   // after deconv2+relu (NCHW)
__device__ int   g_idx[32 * 64 * 64];

// repacked weights
__device__ float  g_wt1 [64 * 3 * 16];          // c1 scalar path
__device__ float  g_wt3 [64 * 128 * 9];         // c3 scalar path
__device__ float  g_wt3d[3 * 64 * 9];           // dc3 flipped -> plain conv
__device__ float2 g_pw1f[4 * 32 * 16 * 32];     // dc1 B, mma-fragment order
__device__ float2 g_pw2f[4 * 64 * 8 * 32];      // dc2 B, fragment order
__device__ float2 g_cw2f[128 * 16 * 32];        // c2  B, fragment order

__device__ float g_loss;

// ---------------- helpers ----------------
__device__ __forceinline__ float cvt_tf32(float x) {
    asm("cvt.rna.tf32.f32 %0, %0;" : "+f"(x));
    return x;
}
__device__ __forceinline__ unsigned long long pk2(float x) {
    unsigned long long r;
    asm("mov.b64 %0, {%1, %1};" : "=l"(r) : "f"(x));
    return r;
}
__device__ __forceinline__ unsigned long long pk(float x, float y) {
    unsigned long long r;
    asm("mov.b64 %0, {%1, %2};" : "=l"(r) : "f"(x), "f"(y));
    return r;
}
__device__ __forceinline__ void fma2(unsigned long long& d,
                                     unsigned long long a, unsigned long long b) {
    asm("fma.rn.f32x2 %0, %1, %2, %0;" : "+l"(d) : "l"(a), "l"(b));
}
__device__ __forceinline__ float2 up2(unsigned long long v) {
    float2 f;
    asm("mov.b64 {%0, %1}, %2;" : "=f"(f.x), "=f"(f.y) : "l"(v));
    return f;
}
__device__ __forceinline__ void mma_tf32(float* c, unsigned a0, unsigned a1,
                                         unsigned a2, unsigned a3,
                                         unsigned b0, unsigned b1) {
    asm volatile(
        "mma.sync.aligned.m16n8k8.row.col.f32.tf32.tf32.f32 "
        "{%0,%1,%2,%3}, {%4,%5,%6,%7}, {%8,%9}, {%0,%1,%2,%3};"
        : "+f"(c[0]), "+f"(c[1]), "+f"(c[2]), "+f"(c[3])
        : "r"(a0), "r"(a1), "r"(a2), "r"(a3), "r"(b0), "r"(b1));
}
__device__ __forceinline__ unsigned smem_u32(const void* p) {
    return (unsigned)__cvta_generic_to_shared(p);
}
__device__ __forceinline__ void cp_async4(unsigned dst, const void* src, bool pred) {
    int sz = pred ? 4 : 0;
    asm volatile("cp.async.ca.shared.global [%0], [%1], 4, %2;"
                 :: "r"(dst), "l"(src), "r"(sz));
}
__device__ __forceinline__ void cp_async16(unsigned dst, const void* src) {
    asm volatile("cp.async.cg.shared.global [%0], [%1], 16;" :: "r"(dst), "l"(src));
}
__device__ __forceinline__ void cp_commit() {
    asm volatile("cp.async.commit_group;");
}
template<int N> __device__ __forceinline__ void cp_wait() {
    asm volatile("cp.async.wait_group %0;" :: "n"(N));
}

// ---------------- weight repack ----------------
__global__ void repack_conv(const float* __restrict__ w, float* __restrict__ wt,
                            int Co, int Ci, int KK) {
    int i = blockIdx.x * blockDim.x + threadIdx.x;
    if (i >= Co * Ci * KK) return;
    int co = i / (Ci * KK);
    int r  = i % (Ci * KK);
    wt[r * Co + co] = w[i];
}
__global__ void repack_deconv_flip(const float* __restrict__ w, float* __restrict__ wt,
                                   int Co, int Ci, int K) {
    int KK = K * K;
    int i = blockIdx.x * blockDim.x + threadIdx.x;
    if (i >= Ci * Co * KK) return;
    int ci = i / (Co * KK);
    int r  = i % (Co * KK);
    int co = r / KK;
    int t  = r % KK;
    int kh = t / K, kw = t % K;
    int tf = (K - 1 - kh) * K + (K - 1 - kw);
    wt[(ci * KK + tf) * Co + co] = w[i];
}
// stride-2 deconv B in mma fragment order:
// out[((p*(CI/2)+s)*NT + nt)*32 + lane] = (w[2s][co]@(kh,kw), w[2s+1][co]@(kh,kw))
// with tap=lane&3, co = nt*8 + (lane>>2). w layout [CI][CO][4][4].
__global__ void repack_par_frag(const float* __restrict__ w, float2* __restrict__ o,
                                int CI, int CO, int NT) {
    int i = blockIdx.x * blockDim.x + threadIdx.x;
    int total = 4 * (CI / 2) * NT * 32;
    if (i >= total) return;
    int lane = i & 31;
    int t1 = i >> 5;
    int nt = t1 % NT;
    int t2 = t1 / NT;
    int s  = t2 % (CI / 2);
    int p  = t2 / (CI / 2);
    int tap = lane & 3;
    int a = tap >> 1, bt = tap & 1;
    int ph = p >> 1, pw = p & 1;
    int kh = ph ? (a ? 0 : 2) : (a ? 3 : 1);
    int kw = pw ? (bt ? 0 : 2) : (bt ? 3 : 1);
    int co = nt * 8 + (lane >> 2);
    float v0 = w[(((2 * s) * CO + co) * 4 + kh) * 4 + kw];
    float v1 = w[(((2 * s + 1) * CO + co) * 4 + kh) * 4 + kw];
    o[i] = make_float2(cvt_tf32(v0), cvt_tf32(v1));
}
// conv2 B fragment order: s = ci*2+th; out[((s)*NT+nt)*32+lane] =
// (w[co][ci][2th][kw], w[co][ci][2th+1][kw]), kw=lane&3, co=nt*8+(lane>>2).
__global__ void repack_c2_frag(const float* __restrict__ w, float2* __restrict__ o,
                               int CI, int CO, int NT) {
    int i = blockIdx.x * blockDim.x + threadIdx.x;
    int total = CI * 2 * NT * 32;
    if (i >= total) return;
    int lane = i & 31;
    int t1 = i >> 5;
    int nt = t1 % NT;
    int s  = t1 / NT;
    int ci = s >> 1, th = s & 1;
    int kw = lane & 3;
    int co = nt * 8 + (lane >> 2);
    float v0 = w[((co * CI + ci) * 4 + 2 * th) * 4 + kw];
    float v1 = w[((co * CI + ci) * 4 + 2 * th + 1) * 4 + kw];
    o[i] = make_float2(cvt_tf32(v0), cvt_tf32(v1));
}

__global__ void zero_loss_k() { g_loss = 0.0f; }
__global__ void finalize_k(float* __restrict__ out, int loss_idx) {
    out[loss_idx] = 1.25f * g_loss * (1.0f / 8388608.0f);
}

// ================= MMA stride-2 deconv, parity-decomposed, pipelined =================
template<int CI, int CO, int MH, int MW, int MWP, int HIN, int WIN, int KC>
__global__ void deconv_mma_k(const float* __restrict__ in, const float2* __restrict__ wf,
                             const float* __restrict__ bias, float* __restrict__ out) {
    constexpr int R = MH + 1;
    constexpr int NT = CO / 8;
    constexpr int PLANE = R * MWP;
    constexpr int ASZ = KC * PLANE;          // floats per buffer
    constexpr int BSZ = (KC / 2) * NT * 32;  // float2 per buffer
    constexpr int NC = CI / KC;
    constexpr int HOUT = 2 * HIN, WOUT = 2 * WIN;
    extern __shared__ float sm[];
    float*  sA = sm;                         // [2][ASZ]
    float2* sB = (float2*)(sm + 2 * ASZ);    // [2][BSZ]

    const int p  = blockIdx.z, ph = p >> 1, pw = p & 1;
    const int tiles_h = HIN / MH;
    const int h0 = (blockIdx.x % tiles_h) * MH;
    const int b  = blockIdx.x / tiles_h;
    const int warp = threadIdx.x >> 5, lane = threadIdx.x & 31;
    const int tap = lane & 3;
    const int a = tap >> 1, bt = tap & 1;
    const int roff = ph ? a : 1 - a;
    const int coff = pw ? bt : 1 - bt;
    const int mbase = warp * 16;
    const int mr = mbase / MW;
    const int colq = (mbase % MW) + 2 * (lane >> 2);   // interleaved m->col
    const int aoff0 = (mr + roff) * MWP + colq + coff;

    float acc[NT][4];
#pragma unroll
    for (int nt = 0; nt < NT; nt++) {
        float b0v = bias[nt * 8 + 2 * (lane & 3)];
        float b1v = bias[nt * 8 + 2 * (lane & 3) + 1];
        acc[nt][0] = b0v; acc[nt][1] = b1v; acc[nt][2] = b0v; acc[nt][3] = b1v;
    }

    const float*  inb = in + (size_t)b * CI * HIN * WIN;
    const float2* wpb = wf + (size_t)p * (CI / 2) * NT * 32;
    const unsigned sAu = smem_u32(sA);
    const unsigned sBu = smem_u32(sB);

    auto stageA = [&](int ci0, int buf) {
        for (int i = threadIdx.x; i < ASZ; i += 256) {
            int ci_l = i / PLANE;
            int rem  = i % PLANE;
            int r = rem / MWP, c = rem % MWP;
            int gr = h0 + r - (ph ? 0 : 1);
            int gc = c - (pw ? 0 : 1);
            bool ok = (unsigned)gr < (unsigned)HIN && (unsigned)gc < (unsigned)WIN;
            const float* src = inb + (size_t)(ci0 + ci_l) * HIN * WIN
                               + (ok ? gr * WIN + gc : 0);
            cp_async4(sAu + (buf * ASZ + i) * 4, src, ok);
        }
    };
    auto stageB = [&](int ci0, int buf) {
        const char* src = (const char*)(wpb + (size_t)(ci0 / 2) * NT * 32);
        for (int i = threadIdx.x; i < BSZ / 2; i += 256)
            cp_async16(sBu + buf * BSZ * 8 + i * 16, src + i * 16);
    };

    stageA(0, 0); stageB(0, 0); cp_commit();
    for (int c = 0; c < NC; c++) {
        int buf = c & 1;
        if (c + 1 < NC) {
            stageA((c + 1) * KC, buf ^ 1);
            stageB((c + 1) * KC, buf ^ 1);
            cp_commit();
            cp_wait<1>();
        } else {
            cp_wait<0>();
        }
        __syncthreads();
        const float*  bA = sA + buf * ASZ;
        const float2* bB = sB + buf * BSZ;
#pragma unroll
        for (int s = 0; s < KC / 2; s++) {
            const float* pa = bA + 2 * s * PLANE + aoff0;
            unsigned a0 = __float_as_uint(pa[0]);
            unsigned a1 = __float_as_uint(pa[1]);          // m+8 -> col+1
            unsigned a2 = __float_as_uint(pa[PLANE]);
            unsigned a3 = __float_as_uint(pa[PLANE + 1]);
            const float2* pb = bB + s * NT * 32 + lane;    // fragment-linear
#pragma unroll
            for (int nt = 0; nt < NT; nt++) {
                float2 bb = pb[nt * 32];
                mma_tf32(acc[nt], a0, a1, a2, a3,
                         __float_as_uint(bb.x), __float_as_uint(bb.y));
            }
        }
        __syncthreads();
    }

    const int ho = 2 * (h0 + mr) + ph;
#pragma unroll
    for (int nt = 0; nt < NT; nt++) {
        int n0 = nt * 8 + 2 * (lane & 3);
#pragma unroll
        for (int j = 0; j < 4; j++) {
            int n  = n0 + (j & 1);
            int wi = colq + (j >> 1);
            int wo = 2 * wi + pw;
            float v = acc[nt][j];
            v = v > 0.0f ? v : 0.0f;
            out[((size_t)(b * CO + n) * HOUT + ho) * WOUT + wo] = v;
        }
    }
}

// ================= MMA conv2 4x4 stride-2, pipelined =================
template<int CI, int CO, int HIN, int WIN, int KC>
__global__ void conv2_mma_k(const float* __restrict__ in, const float2* __restrict__ wf,
                            const float* __restrict__ bias, float* __restrict__ out) {
    constexpr int MH = 2, MW = 64;
    constexpr int R = 6, MWP = 2 * MW + 2;   // 130
    constexpr int NT = CO / 8;
    constexpr int PLANE = R * MWP;
    constexpr int ASZ = KC * PLANE;
    constexpr int BSZ = KC * 2 * NT * 32;    // float2
    constexpr int NC = CI / KC;
    constexpr int HOUT = HIN / 2, WOUT = WIN / 2;
    extern __shared__ float sm[];
    float*  sA = sm;
    float2* sB = (float2*)(sm + 2 * ASZ);

    const int tiles_h = HOUT / MH;
    const int h0 = (blockIdx.x % tiles_h) * MH;
    const int b  = blockIdx.x / tiles_h;
    const int warp = threadIdx.x >> 5, lane = threadIdx.x & 31;
    const int kw = lane & 3;
    const int mbase = warp * 16;
    const int mr = mbase / MW;
    const int colq = (mbase % MW) + 2 * (lane >> 2);

    float acc[NT][4];
#pragma unroll
    for (int nt = 0; nt < NT; nt++) {
        float b0v = bias[nt * 8 + 2 * (lane & 3)];
        float b1v = bias[nt * 8 + 2 * (lane & 3) + 1];
        acc[nt][0] = b0v; acc[nt][1] = b1v; acc[nt][2] = b0v; acc[nt][3] = b1v;
    }

    const float* inb = in + (size_t)b * CI * HIN * WIN;
    const unsigned sAu = smem_u32(sA);
    const unsigned sBu = smem_u32(sB);

    auto stageA = [&](int ci0, int buf) {
        for (int i = threadIdx.x; i < ASZ; i += 256) {
            int ci_l = i / PLANE;
            int rem  = i % PLANE;
            int r = rem / MWP, c = rem % MWP;
            int gr = 2 * h0 + r - 1;
            int gc = c - 1;
            bool ok = (unsigned)gr < (unsigned)HIN && (unsigned)gc < (unsigned)WIN;
            const float* src = inb + (size_t)(ci0 + ci_l) * HIN * WIN
                               + (ok ? gr * WIN + gc : 0);
            cp_async4(sAu + (buf * ASZ + i) * 4, src, ok);
        }
    };
    auto stageB = [&](int ci0, int buf) {
        const char* src = (const char*)(wf + (size_t)(ci0 * 2) * NT * 32);
        for (int i = threadIdx.x; i < BSZ / 2; i += 256)
            cp_async16(sBu + buf * BSZ * 8 + i * 16, src + i * 16);
    };

    stageA(0, 0); stageB(0, 0); cp_commit();
    for (int c = 0; c < NC; c++) {
        int buf = c & 1;
        if (c + 1 < NC) {
            stageA((c + 1) * KC, buf ^ 1);
            stageB((c + 1) * KC, buf ^ 1);
            cp_commit();
            cp_wait<1>();
        } else {
            cp_wait<0>();
        }
        __syncthreads();
        const float*  bA = sA + buf * ASZ;
        const float2* bB = sB + buf * BSZ;
#pragma unroll
        for (int s = 0; s < 2 * KC; s++) {
            int ci_l = s >> 1, th = s & 1;
            const float* pa = bA + ci_l * PLANE + (2 * mr + 2 * th) * MWP
                              + 2 * colq + kw;
            unsigned a0 = __float_as_uint(pa[0]);
            unsigned a1 = __float_as_uint(pa[2]);          // m+8 -> col+1 -> input+2
            unsigned a2 = __float_as_uint(pa[MWP]);
            unsigned a3 = __float_as_uint(pa[MWP + 2]);
            const float2* pb = bB + s * NT * 32 + lane;
#pragma unroll
            for (int nt = 0; nt < NT; nt++) {
                float2 bb = pb[nt * 32];
                mma_tf32(acc[nt], a0, a1, a2, a3,
                         __float_as_uint(bb.x), __float_as_uint(bb.y));
            }
        }
        __syncthreads();
    }

    const int ho = h0 + mr;
#pragma unroll
    for (int nt = 0; nt < NT; nt++) {
        int n0 = nt * 8 + 2 * (lane & 3);
#pragma unroll
        for (int j = 0; j < 4; j++) {
            int n  = n0 + (j & 1);
            int wo = colq + (j >> 1);
            float v = acc[nt][j];
            v = v > 0.0f ? v : 0.0f;
            out[((size_t)(b * CO + n) * HOUT + ho) * WOUT + wo] = v;
        }
    }
}

// ---------------- conv + relu, f32x2 (c1, c3) ----------------
template<int CI, int K, int CO, int COT, int WT,
         int HIN, int WIN, int HOUT, int WOUT, int ST, int PD>
__global__ void conv_f2_k(const float* __restrict__ in, const float* __restrict__ wt,
                          const float* __restrict__ bias, float* __restrict__ out) {
    extern __shared__ float ws[];
    const int cob = blockIdx.y * COT;
    const int WROWS = CI * K * K;
    for (int i = threadIdx.x; i < WROWS * COT; i += 256) {
        int r = i / COT, c = i % COT;
        ws[i] = wt[r * CO + cob + c];
    }
    __syncthreads();

    const int warp = threadIdx.x >> 5, lane = threadIdx.x & 31;
    const int SPR = WOUT / (32 * WT);
    int seg = blockIdx.x * 8 + warp;
    int s   = seg % SPR;
    int row = seg / SPR;
    int h   = row % HOUT;
    int b   = row / HOUT;

    int wcol[WT];
#pragma unroll
    for (int k = 0; k < WT; k++) wcol[k] = s * 32 * WT + lane + 32 * k;

    unsigned long long acc[WT][COT / 2];
#pragma unroll
    for (int k = 0; k < WT; k++)
#pragma unroll
        for (int j = 0; j < COT / 2; j++)
            acc[k][j] = pk(bias[cob + 2 * j], bias[cob + 2 * j + 1]);

    const float* inb = in + (size_t)b * CI * HIN * WIN;
#pragma unroll 2
    for (int ci = 0; ci < CI; ci++) {
        const float* inp = inb + (size_t)ci * HIN * WIN;
#pragma unroll
        for (int kh = 0; kh < K; kh++) {
            int hi = h * ST - PD + kh;
            if ((unsigned)hi >= (unsigned)HIN) continue;
            const float* rp = inp + hi * WIN;
#pragma unroll
            for (int kw = 0; kw < K; kw++) {
                const ulonglong2* wv = reinterpret_cast<const ulonglong2*>(
                    ws + (ci * (K * K) + kh * K + kw) * COT);
                unsigned long long vv[WT];
#pragma unroll
                for (int k = 0; k < WT; k++) {
                    int wi = wcol[k] * ST - PD + kw;
                    float v = ((unsigned)wi < (unsigned)WIN) ? rp[wi] : 0.0f;
                    vv[k] = pk2(v);
                }
#pragma unroll
                for (int j = 0; j < COT / 4; j++) {
                    ulonglong2 w2 = wv[j];
#pragma unroll
                    for (int k = 0; k < WT; k++) {
                        fma2(acc[k][2 * j], vv[k], w2.x);
                        fma2(acc[k][2 * j + 1], vv[k], w2.y);
                    }
                }
            }
        }
    }

    size_t obase = ((size_t)b * CO + cob) * HOUT * WOUT + (size_t)h * WOUT;
#pragma unroll
    for (int k = 0; k < WT; k++)
#pragma unroll
        for (int j = 0; j < COT / 2; j++) {
            float2 r = up2(acc[k][j]);
            float v0 = r.x > 0.0f ? r.x : 0.0f;
            float v1 = r.y > 0.0f ? r.y : 0.0f;
            out[obase + (size_t)(2 * j) * HOUT * WOUT + wcol[k]] = v0;
            out[obase + (size_t)(2 * j + 1) * HOUT * WOUT + wcol[k]] = v1;
        }
}

// ---------------- small-CO stride-1 conv + sigmoid (dc3) ----------------
template<int CI, int K, int CO, int WT, int HIN, int WIN, int PD>
__global__ void conv_sig_k(const float* __restrict__ in, const float* __restrict__ wt,
                           const float* __restrict__ bias, float* __restrict__ out) {
    constexpr int HOUT = HIN, WOUT = WIN;
    extern __shared__ float ws[];
    for (int i = threadIdx.x; i < CI * K * K * CO; i += 256) ws[i] = wt[i];
    __syncthreads();

    const int warp = threadIdx.x >> 5, lane = threadIdx.x & 31;
    const int SPR = WOUT / (32 * WT);
    int seg = blockIdx.x * 8 + warp;
    int s   = seg % SPR;
    int row = seg / SPR;
    int h   = row % HOUT;
    int b   = row / HOUT;

    int wcol[WT];
#pragma unroll
    for (int k = 0; k < WT; k++) wcol[k] = s * 32 * WT + lane + 32 * k;

    float acc[WT][CO];
#pragma unroll
    for (int k = 0; k < WT; k++)
#pragma unroll
        for (int c = 0; c < CO; c++) acc[k][c] = bias[c];

    const float* inb = in + (size_t)b * CI * HIN * WIN;
#pragma unroll 2
    for (int ci = 0; ci < CI; ci++) {
        const float* inp = inb + (size_t)ci * HIN * WIN;
#pragma unroll
        for (int kh = 0; kh < K; kh++) {
            int hi = h - PD + kh;
            if ((unsigned)hi >= (unsigned)HIN) continue;
            const float* rp = inp + hi * WIN;
#pragma unroll
            for (int kw = 0; kw < K; kw++) {
                const float* wr = ws + (ci * (K * K) + kh * K + kw) * CO;
                float v[WT];
#pragma unroll
                for (int k = 0; k < WT; k++) {
                    int wi = wcol[k] - PD + kw;
                    v[k] = ((unsigned)wi < (unsigned)WIN) ? rp[wi] : 0.0f;
                }
#pragma unroll
                for (int c = 0; c < CO; c++) {
                    float w = wr[c];
#pragma unroll
                    for (int k = 0; k < WT; k++) acc[k][c] += v[k] * w;
                }
            }
        }
    }

    size_t obase = (size_t)b * CO * HOUT * WOUT + (size_t)h * WOUT;
#pragma unroll
    for (int k = 0; k < WT; k++)
#pragma unroll
        for (int c = 0; c < CO; c++) {
            float v = 1.0f / (1.0f + expf(-acc[k][c]));
            out[obase + (size_t)c * HOUT * WOUT + wcol[k]] = v;
        }
}

// ---------------- vector quantize (z NCHW) -> indices + loss ----------------
__global__ void vq_k(const float* __restrict__ emb, const float* __restrict__ z,
                     int* __restrict__ idx) {
    extern __shared__ float sm[];
    float* se = sm;
    float* sn = sm + 512 * 64;
    for (int i = threadIdx.x; i < 512 * 64; i += blockDim.x) se[i] = emb[i];
    __syncthreads();
    for (int k = threadIdx.x; k < 512; k += blockDim.x) {
        float s = 0.0f;
#pragma unroll
        for (int j = 0; j < 64; j++) { float e = se[k * 64 + j]; s += e * e; }
        sn[k] = s;
    }
    __syncthreads();

    int n = blockIdx.x * blockDim.x + threadIdx.x;
    int b  = n >> 12;
    int hw = n & 4095;
    const float* zp = z + (size_t)b * 262144 + hw;
    float zr[64];
#pragma unroll
    for (int j = 0; j < 64; j++) zr[j] = zp[(size_t)j * 4096];

    float best = 3.4e38f;
    int bi = 0;
    for (int k = 0; k < 512; k++) {
        const float4* e4 = reinterpret_cast<const float4*>(se + k * 64);
        float dot = 0.0f;
#pragma unroll
        for (int j = 0; j < 16; j++) {
            float4 e = e4[j];
            dot += zr[4 * j]     * e.x;
            dot += zr[4 * j + 1] * e.y;
            dot += zr[4 * j + 2] * e.z;
            dot += zr[4 * j + 3] * e.w;
        }
        float d = sn[k] - 2.0f * dot;
        if (d < best) { best = d; bi = k; }
    }

    idx[n] = bi;
    float ls = 0.0f;
#pragma unroll
    for (int j = 0; j < 64; j++) {
        float df = se[bi * 64 + j] - zr[j];
        ls += df * df;
    }
#pragma unroll
    for (int o = 16; o > 0; o >>= 1) ls += __shfl_xor_sync(0xffffffffu, ls, o);
    if ((threadIdx.x & 31) == 0) atomicAdd(&g_loss, ls);
}

__global__ void gather_q_k(const float* __restrict__ emb, const int* __restrict__ idx,
                           float* __restrict__ q) {
    int i = blockIdx.x * blockDim.x + threadIdx.x;
    int hw = i & 4095;
    int t  = i >> 12;
    int c  = t & 63;
    int b  = t >> 6;
    q[i] = emb[idx[(b << 12) + hw] * 64 + c];
}

// ---------------- host ----------------
static float* sym_addr(const void* sym) {
    void* p = nullptr;
    cudaGetSymbolAddress(&p, sym);
    return (float*)p;
}

extern "C" void kernel_launch(void* const* d_in, const int* in_sizes, int n_in,
                              void* d_out, int out_size) {
    const float* x   = (const float*)d_in[0];
    const float* w1  = (const float*)d_in[1];
    const float* b1  = (const float*)d_in[2];
    const float* w2  = (const float*)d_in[3];
    const float* b2  = (const float*)d_in[4];
    const float* w3  = (const float*)d_in[5];
    const float* b3  = (const float*)d_in[6];
    const float* emb = (const float*)d_in[7];
    const float* dw1 = (const float*)d_in[8];
    const float* db1 = (const float*)d_in[9];
    const float* dw2 = (const float*)d_in[10];
    const float* db2 = (const float*)d_in[11];
    const float* dw3 = (const float*)d_in[12];
    const float* db3 = (const float*)d_in[13];
    float* out = (float*)d_out;

    float*  h1   = sym_addr(g_h1);
    float*  h2   = sym_addr(g_h2);
    float*  z    = sym_addr(g_z);
    float*  q    = sym_addr(g_q);
    float*  d1   = sym_addr(g_d1);
    float*  d2   = sym_addr(g_d2);
    float*  wt1  = sym_addr(g_wt1);
    float*  wt3  = sym_addr(g_wt3);
    float*  wt3d = sym_addr(g_wt3d);
    float2* pw1f = (float2*)sym_addr(g_pw1f);
    float2* pw2f = (float2*)sym_addr(g_pw2f);
    float2* cw2f = (float2*)sym_addr(g_cw2f);
    int*    idx  = (int*)sym_addr(g_idx);

    auto c1  = conv_f2_k<3, 4, 64, 32, 2, 256, 256, 128, 128, 2, 1>;
    auto c2m = conv2_mma_k<64, 128, 128, 128, 4>;
    auto c3  = conv_f2_k<128, 3, 64, 32, 2, 64, 64, 64, 64, 1, 1>;
    auto dc1 = deconv_mma_k<64, 128, 2, 64, 80, 64, 64, 8>;
    auto dc2 = deconv_mma_k<128, 64, 1, 128, 144, 128, 128, 8>;
    auto dc3 = conv_sig_k<64, 3, 3, 4, 256, 256, 1>;

    // smem sizes
    const int smem_c2  = 2 * (4 * 6 * 130) * 4 + 2 * (4 * 2 * 16 * 32) * 8;  // 90496
    const int smem_dc1 = 2 * (8 * 3 * 80) * 4 + 2 * (4 * 16 * 32) * 8;       // 48128
    const int smem_dc2 = 2 * (8 * 2 * 144) * 4 + 2 * (4 * 8 * 32) * 8;       // 34816

    cudaFuncSetAttribute(c3,  cudaFuncAttributeMaxDynamicSharedMemorySize, 128 * 9 * 32 * 4);
    cudaFuncSetAttribute(c2m, cudaFuncAttributeMaxDynamicSharedMemorySize, smem_c2);
    cudaFuncSetAttribute(dc1, cudaFuncAttributeMaxDynamicSharedMemorySize, smem_dc1);
    cudaFuncSetAttribute(dc2, cudaFuncAttributeMaxDynamicSharedMemorySize, smem_dc2);
    cudaFuncSetAttribute(vq_k, cudaFuncAttributeMaxDynamicSharedMemorySize, (512 * 64 + 512) * 4);

    // repack weights
    repack_conv<<<(64 * 3 * 16 + 255) / 256, 256>>>(w1, wt1, 64, 3, 16);
    repack_c2_frag<<<(64 * 2 * 16 * 32) / 256, 256>>>(w2, cw2f, 64, 128, 16);
    repack_conv<<<(64 * 128 * 9 + 255) / 256, 256>>>(w3, wt3, 64, 128, 9);
    repack_par_frag<<<(4 * 32 * 16 * 32) / 256, 256>>>(dw1, pw1f, 64, 128, 16);
    repack_par_frag<<<(4 * 64 * 8 * 32) / 256, 256>>>(dw2, pw2f, 128, 64, 8);
    repack_deconv_flip<<<(64 * 3 * 9 + 255) / 256, 256>>>(dw3, wt3d, 3, 64, 3);
    zero_loss_k<<<1, 1>>>();

    // encoder
    c1<<<dim3(1024, 2), 256, 3 * 16 * 32 * 4>>>(x, wt1, b1, h1);
    c2m<<<dim3(32 * 32), 256, smem_c2>>>(h1, cw2f, b2, h2);
    c3<<<dim3(256, 2), 256, 128 * 9 * 32 * 4>>>(h2, wt3, b3, z);

    // vector quantize
    vq_k<<<512, 256, (512 * 64 + 512) * 4>>>(emb, z, idx);
    gather_q_k<<<(32 * 64 * 4096) / 256, 256>>>(emb, idx, q);

    // decoder
    dc1<<<dim3(32 * 32, 1, 4), 256, smem_dc1>>>(q, pw1f, db1, d1);
    dc2<<<dim3(128 * 32, 1, 4), 256, smem_dc2>>>(d1, pw2f, db2, d2);
    dc3<<<dim3(2048, 1), 256, 64 * 9 * 3 * 4>>>(d2, wt3d, db3, out);

    finalize_k<<<1, 1>>>(out, out_size - 1);
}

// round 6
// speedup vs baseline: 14.6630x; 1.2444x over previous
#include <cuda_runtime.h>
#include <math.h>

// ---------------- scratch (device globals: allocation-free rule) ----------------
__device__ float g_h1[32u * 64 * 128 * 128];   // after conv1+relu   (NCHW, tf32-rounded)
__device__ float g_h2[32u * 128 * 64 * 64];    // after conv2+relu   (NCHW, tf32-rounded)
__device__ float g_z [32u * 64 * 64 * 64];     // after conv3+relu   (NCHW, fp32)
__device__ float g_q [32u * 64 * 64 * 64];     // quantized          (NCHW, tf32-rounded)
__device__ float g_d1[32u * 128 * 128 * 128];  // after deconv1+relu (NCHW, tf32-rounded)
__device__ float g_d2[32u * 64 * 256 * 256];   // after deconv2+relu (NCHW, fp32)
__device__ int   g_idx[32 * 64 * 64];

// repacked weights
__device__ float  g_wt1 [64 * 3 * 16];          // c1 scalar path
__device__ float  g_wt3d[3 * 64 * 9];           // dc3 flipped -> plain conv
__device__ float2 g_pw1f[4 * 32 * 16 * 32];     // dc1 B, mma-fragment order
__device__ float2 g_pw2f[4 * 64 * 8 * 32];      // dc2 B, fragment order
__device__ float2 g_cw2f[128 * 16 * 32];        // c2  B, fragment order
__device__ float2 g_cw3f[64 * 3 * 8 * 32];      // c3  B, fragment order (12 taps, kw=3 zeroed)

__device__ float g_loss;

// ---------------- helpers ----------------
__device__ __forceinline__ float cvt_tf32(float x) {
    asm("cvt.rna.tf32.f32 %0, %0;" : "+f"(x));
    return x;
}
__device__ __forceinline__ unsigned long long pk2(float x) {
    unsigned long long r;
    asm("mov.b64 %0, {%1, %1};" : "=l"(r) : "f"(x));
    return r;
}
__device__ __forceinline__ unsigned long long pk(float x, float y) {
    unsigned long long r;
    asm("mov.b64 %0, {%1, %2};" : "=l"(r) : "f"(x), "f"(y));
    return r;
}
__device__ __forceinline__ void fma2(unsigned long long& d,
                                     unsigned long long a, unsigned long long b) {
    asm("fma.rn.f32x2 %0, %1, %2, %0;" : "+l"(d) : "l"(a), "l"(b));
}
__device__ __forceinline__ float2 up2(unsigned long long v) {
    float2 f;
    asm("mov.b64 {%0, %1}, %2;" : "=f"(f.x), "=f"(f.y) : "l"(v));
    return f;
}
__device__ __forceinline__ void mma_tf32(float* c, unsigned a0, unsigned a1,
                                         unsigned a2, unsigned a3,
                                         unsigned b0, unsigned b1) {
    asm volatile(
        "mma.sync.aligned.m16n8k8.row.col.f32.tf32.tf32.f32 "
        "{%0,%1,%2,%3}, {%4,%5,%6,%7}, {%8,%9}, {%0,%1,%2,%3};"
        : "+f"(c[0]), "+f"(c[1]), "+f"(c[2]), "+f"(c[3])
        : "r"(a0), "r"(a1), "r"(a2), "r"(a3), "r"(b0), "r"(b1));
}
__device__ __forceinline__ unsigned smem_u32(const void* p) {
    return (unsigned)__cvta_generic_to_shared(p);
}
__device__ __forceinline__ void cp_async4(unsigned dst, const void* src, bool pred) {
    int sz = pred ? 4 : 0;
    asm volatile("cp.async.ca.shared.global [%0], [%1], 4, %2;"
                 :: "r"(dst), "l"(src), "r"(sz));
}
__device__ __forceinline__ void cp_async16(unsigned dst, const void* src) {
    asm volatile("cp.async.cg.shared.global [%0], [%1], 16;" :: "r"(dst), "l"(src));
}
__device__ __forceinline__ void cp_commit() {
    asm volatile("cp.async.commit_group;");
}
template<int N> __device__ __forceinline__ void cp_wait() {
    asm volatile("cp.async.wait_group %0;" :: "n"(N));
}

// ---------------- weight repack ----------------
__global__ void repack_conv(const float* __restrict__ w, float* __restrict__ wt,
                            int Co, int Ci, int KK) {
    int i = blockIdx.x * blockDim.x + threadIdx.x;
    if (i >= Co * Ci * KK) return;
    int co = i / (Ci * KK);
    int r  = i % (Ci * KK);
    wt[r * Co + co] = w[i];
}
__global__ void repack_deconv_flip(const float* __restrict__ w, float* __restrict__ wt,
                                   int Co, int Ci, int K) {
    int KK = K * K;
    int i = blockIdx.x * blockDim.x + threadIdx.x;
    if (i >= Ci * Co * KK) return;
    int ci = i / (Co * KK);
    int r  = i % (Co * KK);
    int co = r / KK;
    int t  = r % KK;
    int kh = t / K, kw = t % K;
    int tf = (K - 1 - kh) * K + (K - 1 - kw);
    wt[(ci * KK + tf) * Co + co] = w[i];
}
// stride-2 deconv B in mma fragment order.
__global__ void repack_par_frag(const float* __restrict__ w, float2* __restrict__ o,
                                int CI, int CO, int NT) {
    int i = blockIdx.x * blockDim.x + threadIdx.x;
    int total = 4 * (CI / 2) * NT * 32;
    if (i >= total) return;
    int lane = i & 31;
    int t1 = i >> 5;
    int nt = t1 % NT;
    int t2 = t1 / NT;
    int s  = t2 % (CI / 2);
    int p  = t2 / (CI / 2);
    int tap = lane & 3;
    int a = tap >> 1, bt = tap & 1;
    int ph = p >> 1, pw = p & 1;
    int kh = ph ? (a ? 0 : 2) : (a ? 3 : 1);
    int kw = pw ? (bt ? 0 : 2) : (bt ? 3 : 1);
    int co = nt * 8 + (lane >> 2);
    float v0 = w[(((2 * s) * CO + co) * 4 + kh) * 4 + kw];
    float v1 = w[(((2 * s + 1) * CO + co) * 4 + kh) * 4 + kw];
    o[i] = make_float2(cvt_tf32(v0), cvt_tf32(v1));
}
// conv2 B fragment order.
__global__ void repack_c2_frag(const float* __restrict__ w, float2* __restrict__ o,
                               int CI, int CO, int NT) {
    int i = blockIdx.x * blockDim.x + threadIdx.x;
    int total = CI * 2 * NT * 32;
    if (i >= total) return;
    int lane = i & 31;
    int t1 = i >> 5;
    int nt = t1 % NT;
    int s  = t1 / NT;
    int ci = s >> 1, th = s & 1;
    int kw = lane & 3;
    int co = nt * 8 + (lane >> 2);
    float v0 = w[((co * CI + ci) * 4 + 2 * th) * 4 + kw];
    float v1 = w[((co * CI + ci) * 4 + 2 * th + 1) * 4 + kw];
    o[i] = make_float2(cvt_tf32(v0), cvt_tf32(v1));
}
// c3 (3x3 s1) B fragment order: [ci_pair s][g=kh][nt][lane]; kw=lane&3, zero at kw==3.
__global__ void repack_c3_frag(const float* __restrict__ w, float2* __restrict__ o,
                               int CI, int CO, int NT) {
    int i = blockIdx.x * blockDim.x + threadIdx.x;
    int total = (CI / 2) * 3 * NT * 32;
    if (i >= total) return;
    int lane = i & 31;
    int t1 = i >> 5;
    int nt = t1 % NT;
    int t2 = t1 / NT;
    int g  = t2 % 3;
    int s  = t2 / 3;
    int kw = lane & 3;
    int co = nt * 8 + (lane >> 2);
    float v0 = 0.0f, v1 = 0.0f;
    if (kw < 3) {
        v0 = w[((co * CI + 2 * s) * 3 + g) * 3 + kw];
        v1 = w[((co * CI + 2 * s + 1) * 3 + g) * 3 + kw];
    }
    o[i] = make_float2(cvt_tf32(v0), cvt_tf32(v1));
}

__global__ void zero_loss_k() { g_loss = 0.0f; }
__global__ void finalize_k(float* __restrict__ out, int loss_idx) {
    out[loss_idx] = 1.25f * g_loss * (1.0f / 8388608.0f);
}

// ================= MMA stride-2 deconv, parity-decomposed, pipelined =================
template<int CI, int CO, int MH, int MW, int MWP, int HIN, int WIN, int KC, bool RND>
__global__ void deconv_mma_k(const float* __restrict__ in, const float2* __restrict__ wf,
                             const float* __restrict__ bias, float* __restrict__ out) {
    constexpr int R = MH + 1;
    constexpr int NT = CO / 8;
    constexpr int PLANE = R * MWP;
    constexpr int ASZ = KC * PLANE;
    constexpr int BSZ = (KC / 2) * NT * 32;
    constexpr int NC = CI / KC;
    constexpr int HOUT = 2 * HIN, WOUT = 2 * WIN;
    extern __shared__ float sm[];
    float*  sA = sm;
    float2* sB = (float2*)(sm + 2 * ASZ);

    const int p  = blockIdx.z, ph = p >> 1, pw = p & 1;
    const int tiles_h = HIN / MH;
    const int h0 = (blockIdx.x % tiles_h) * MH;
    const int b  = blockIdx.x / tiles_h;
    const int warp = threadIdx.x >> 5, lane = threadIdx.x & 31;
    const int tap = lane & 3;
    const int a = tap >> 1, bt = tap & 1;
    const int roff = ph ? a : 1 - a;
    const int coff = pw ? bt : 1 - bt;
    const int mbase = warp * 16;
    const int mr = mbase / MW;
    const int colq = (mbase % MW) + 2 * (lane >> 2);
    const int aoff0 = (mr + roff) * MWP + colq + coff;

    float acc[NT][4];
#pragma unroll
    for (int nt = 0; nt < NT; nt++) {
        float b0v = bias[nt * 8 + 2 * (lane & 3)];
        float b1v = bias[nt * 8 + 2 * (lane & 3) + 1];
        acc[nt][0] = b0v; acc[nt][1] = b1v; acc[nt][2] = b0v; acc[nt][3] = b1v;
    }

    const float*  inb = in + (size_t)b * CI * HIN * WIN;
    const float2* wpb = wf + (size_t)p * (CI / 2) * NT * 32;
    const unsigned sAu = smem_u32(sA);
    const unsigned sBu = smem_u32(sB);

    auto stageA = [&](int ci0, int buf) {
        for (int i = threadIdx.x; i < ASZ; i += 256) {
            int ci_l = i / PLANE;
            int rem  = i % PLANE;
            int r = rem / MWP, c = rem % MWP;
            int gr = h0 + r - (ph ? 0 : 1);
            int gc = c - (pw ? 0 : 1);
            bool ok = (unsigned)gr < (unsigned)HIN && (unsigned)gc < (unsigned)WIN;
            const float* src = inb + (size_t)(ci0 + ci_l) * HIN * WIN
                               + (ok ? gr * WIN + gc : 0);
            cp_async4(sAu + (buf * ASZ + i) * 4, src, ok);
        }
    };
    auto stageB = [&](int ci0, int buf) {
        const char* src = (const char*)(wpb + (size_t)(ci0 / 2) * NT * 32);
        for (int i = threadIdx.x; i < BSZ / 2; i += 256)
            cp_async16(sBu + buf * BSZ * 8 + i * 16, src + i * 16);
    };

    stageA(0, 0); stageB(0, 0); cp_commit();
    for (int c = 0; c < NC; c++) {
        int buf = c & 1;
        if (c + 1 < NC) {
            stageA((c + 1) * KC, buf ^ 1);
            stageB((c + 1) * KC, buf ^ 1);
            cp_commit();
            cp_wait<1>();
        } else {
            cp_wait<0>();
        }
        __syncthreads();
        const float*  bA = sA + buf * ASZ;
        const float2* bB = sB + buf * BSZ;
#pragma unroll
        for (int s = 0; s < KC / 2; s++) {
            const float* pa = bA + 2 * s * PLANE + aoff0;
            unsigned a0 = __float_as_uint(pa[0]);
            unsigned a1 = __float_as_uint(pa[1]);
            unsigned a2 = __float_as_uint(pa[PLANE]);
            unsigned a3 = __float_as_uint(pa[PLANE + 1]);
            const float2* pb = bB + s * NT * 32 + lane;
#pragma unroll
            for (int nt = 0; nt < NT; nt++) {
                float2 bb = pb[nt * 32];
                mma_tf32(acc[nt], a0, a1, a2, a3,
                         __float_as_uint(bb.x), __float_as_uint(bb.y));
            }
        }
        __syncthreads();
    }

    const int ho = 2 * (h0 + mr) + ph;
#pragma unroll
    for (int nt = 0; nt < NT; nt++) {
        int n0 = nt * 8 + 2 * (lane & 3);
#pragma unroll
        for (int j = 0; j < 4; j++) {
            int n  = n0 + (j & 1);
            int wi = colq + (j >> 1);
            int wo = 2 * wi + pw;
            float v = acc[nt][j];
            v = v > 0.0f ? v : 0.0f;
            if (RND) v = cvt_tf32(v);
            out[((size_t)(b * CO + n) * HOUT + ho) * WOUT + wo] = v;
        }
    }
}

// ================= MMA conv2 4x4 stride-2, pipelined =================
template<int CI, int CO, int HIN, int WIN, int KC, bool RND>
__global__ void conv2_mma_k(const float* __restrict__ in, const float2* __restrict__ wf,
                            const float* __restrict__ bias, float* __restrict__ out) {
    constexpr int MH = 2, MW = 64;
    constexpr int R = 6, MWP = 2 * MW + 2;
    constexpr int NT = CO / 8;
    constexpr int PLANE = R * MWP;
    constexpr int ASZ = KC * PLANE;
    constexpr int BSZ = KC * 2 * NT * 32;
    constexpr int NC = CI / KC;
    constexpr int HOUT = HIN / 2, WOUT = WIN / 2;
    extern __shared__ float sm[];
    float*  sA = sm;
    float2* sB = (float2*)(sm + 2 * ASZ);

    const int tiles_h = HOUT / MH;
    const int h0 = (blockIdx.x % tiles_h) * MH;
    const int b  = blockIdx.x / tiles_h;
    const int warp = threadIdx.x >> 5, lane = threadIdx.x & 31;
    const int kw = lane & 3;
    const int mbase = warp * 16;
    const int mr = mbase / MW;
    const int colq = (mbase % MW) + 2 * (lane >> 2);

    float acc[NT][4];
#pragma unroll
    for (int nt = 0; nt < NT; nt++) {
        float b0v = bias[nt * 8 + 2 * (lane & 3)];
        float b1v = bias[nt * 8 + 2 * (lane & 3) + 1];
        acc[nt][0] = b0v; acc[nt][1] = b1v; acc[nt][2] = b0v; acc[nt][3] = b1v;
    }

    const float* inb = in + (size_t)b * CI * HIN * WIN;
    const unsigned sAu = smem_u32(sA);
    const unsigned sBu = smem_u32(sB);

    auto stageA = [&](int ci0, int buf) {
        for (int i = threadIdx.x; i < ASZ; i += 256) {
            int ci_l = i / PLANE;
            int rem  = i % PLANE;
            int r = rem / MWP, c = rem % MWP;
            int gr = 2 * h0 + r - 1;
            int gc = c - 1;
            bool ok = (unsigned)gr < (unsigned)HIN && (unsigned)gc < (unsigned)WIN;
            const float* src = inb + (size_t)(ci0 + ci_l) * HIN * WIN
                               + (ok ? gr * WIN + gc : 0);
            cp_async4(sAu + (buf * ASZ + i) * 4, src, ok);
        }
    };
    auto stageB = [&](int ci0, int buf) {
        const char* src = (const char*)(wf + (size_t)(ci0 * 2) * NT * 32);
        for (int i = threadIdx.x; i < BSZ / 2; i += 256)
            cp_async16(sBu + buf * BSZ * 8 + i * 16, src + i * 16);
    };

    stageA(0, 0); stageB(0, 0); cp_commit();
    for (int c = 0; c < NC; c++) {
        int buf = c & 1;
        if (c + 1 < NC) {
            stageA((c + 1) * KC, buf ^ 1);
            stageB((c + 1) * KC, buf ^ 1);
            cp_commit();
            cp_wait<1>();
        } else {
            cp_wait<0>();
        }
        __syncthreads();
        const float*  bA = sA + buf * ASZ;
        const float2* bB = sB + buf * BSZ;
#pragma unroll
        for (int s = 0; s < 2 * KC; s++) {
            int ci_l = s >> 1, th = s & 1;
            const float* pa = bA + ci_l * PLANE + (2 * mr + 2 * th) * MWP
                              + 2 * colq + kw;
            unsigned a0 = __float_as_uint(pa[0]);
            unsigned a1 = __float_as_uint(pa[2]);
            unsigned a2 = __float_as_uint(pa[MWP]);
            unsigned a3 = __float_as_uint(pa[MWP + 2]);
            const float2* pb = bB + s * NT * 32 + lane;
#pragma unroll
            for (int nt = 0; nt < NT; nt++) {
                float2 bb = pb[nt * 32];
                mma_tf32(acc[nt], a0, a1, a2, a3,
                         __float_as_uint(bb.x), __float_as_uint(bb.y));
            }
        }
        __syncthreads();
    }

    const int ho = h0 + mr;
#pragma unroll
    for (int nt = 0; nt < NT; nt++) {
        int n0 = nt * 8 + 2 * (lane & 3);
#pragma unroll
        for (int j = 0; j < 4; j++) {
            int n  = n0 + (j & 1);
            int wo = colq + (j >> 1);
            float v = acc[nt][j];
            v = v > 0.0f ? v : 0.0f;
            if (RND) v = cvt_tf32(v);
            out[((size_t)(b * CO + n) * HOUT + ho) * WOUT + wo] = v;
        }
    }
}

// ================= MMA conv3x3 stride-1 (c3), taps padded to 12, pipelined =================
template<int CI, int CO, int HW, int KC>
__global__ void conv3_mma_k(const float* __restrict__ in, const float2* __restrict__ wf,
                            const float* __restrict__ bias, float* __restrict__ out) {
    constexpr int MH = 2, MW = 64;
    constexpr int R = MH + 2;                // 4 input rows
    constexpr int MWP = 80;                  // 64+3 padded to =16 mod 32
    constexpr int NT = CO / 8;               // 8
    constexpr int PLANE = R * MWP;
    constexpr int ASZ = KC * PLANE;
    constexpr int BSZ = (KC / 2) * 3 * NT * 32;   // float2
    constexpr int NC = CI / KC;
    extern __shared__ float sm[];
    float*  sA = sm;
    float2* sB = (float2*)(sm + 2 * ASZ);

    const int tiles_h = HW / MH;
    const int h0 = (blockIdx.x % tiles_h) * MH;
    const int b  = blockIdx.x / tiles_h;
    const int warp = threadIdx.x >> 5, lane = threadIdx.x & 31;
    const int mbase = warp * 16;
    const int mr = mbase / MW;
    const int colq = (mbase % MW) + 2 * (lane >> 2);

    float acc[NT][4];
#pragma unroll
    for (int nt = 0; nt < NT; nt++) {
        float b0v = bias[nt * 8 + 2 * (lane & 3)];
        float b1v = bias[nt * 8 + 2 * (lane & 3) + 1];
        acc[nt][0] = b0v; acc[nt][1] = b1v; acc[nt][2] = b0v; acc[nt][3] = b1v;
    }

    const float* inb = in + (size_t)b * CI * HW * HW;
    const unsigned sAu = smem_u32(sA);
    const unsigned sBu = smem_u32(sB);

    auto stageA = [&](int ci0, int buf) {
        for (int i = threadIdx.x; i < ASZ; i += 256) {
            int ci_l = i / PLANE;
            int rem  = i % PLANE;
            int r = rem / MWP, c = rem % MWP;
            int gr = h0 + r - 1;
            int gc = c - 1;
            bool ok = (unsigned)gr < (unsigned)HW && (unsigned)gc < (unsigned)HW;
            const float* src = inb + (size_t)(ci0 + ci_l) * HW * HW
                               + (ok ? gr * HW + gc : 0);
            cp_async4(sAu + (buf * ASZ + i) * 4, src, ok);
        }
    };
    auto stageB = [&](int ci0, int buf) {
        const char* src = (const char*)(wf + (size_t)(ci0 / 2) * 3 * NT * 32);
        for (int i = threadIdx.x; i < BSZ / 2; i += 256)
            cp_async16(sBu + buf * BSZ * 8 + i * 16, src + i * 16);
    };

    stageA(0, 0); stageB(0, 0); cp_commit();
    for (int c = 0; c < NC; c++) {
        int buf = c & 1;
        if (c + 1 < NC) {
            stageA((c + 1) * KC, buf ^ 1);
            stageB((c + 1) * KC, buf ^ 1);
            cp_commit();
            cp_wait<1>();
        } else {
            cp_wait<0>();
        }
        __syncthreads();
        const float*  bA = sA + buf * ASZ;
        const float2* bB = sB + buf * BSZ;
#pragma unroll
        for (int s = 0; s < KC / 2; s++) {
#pragma unroll
            for (int g = 0; g < 3; g++) {
                const float* pa = bA + 2 * s * PLANE + (mr + g) * MWP
                                  + colq + (lane & 3);
                unsigned a0 = __float_as_uint(pa[0]);
                unsigned a1 = __float_as_uint(pa[1]);
                unsigned a2 = __float_as_uint(pa[PLANE]);
                unsigned a3 = __float_as_uint(pa[PLANE + 1]);
                const float2* pb = bB + (s * 3 + g) * NT * 32 + lane;
#pragma unroll
                for (int nt = 0; nt < NT; nt++) {
                    float2 bb = pb[nt * 32];
                    mma_tf32(acc[nt], a0, a1, a2, a3,
                             __float_as_uint(bb.x), __float_as_uint(bb.y));
                }
            }
        }
        __syncthreads();
    }

    const int ho = h0 + mr;
#pragma unroll
    for (int nt = 0; nt < NT; nt++) {
        int n0 = nt * 8 + 2 * (lane & 3);
#pragma unroll
        for (int j = 0; j < 4; j++) {
            int n  = n0 + (j & 1);
            int wo = colq + (j >> 1);
            float v = acc[nt][j];
            v = v > 0.0f ? v : 0.0f;
            out[((size_t)(b * CO + n) * HW + ho) * HW + wo] = v;
        }
    }
}

// ---------------- conv + relu, f32x2 (c1) ----------------
template<int CI, int K, int CO, int COT, int WT,
         int HIN, int WIN, int HOUT, int WOUT, int ST, int PD, bool RND>
__global__ void conv_f2_k(const float* __restrict__ in, const float* __restrict__ wt,
                          const float* __restrict__ bias, float* __restrict__ out) {
    extern __shared__ float ws[];
    const int cob = blockIdx.y * COT;
    const int WROWS = CI * K * K;
    for (int i = threadIdx.x; i < WROWS * COT; i += 256) {
        int r = i / COT, c = i % COT;
        ws[i] = wt[r * CO + cob + c];
    }
    __syncthreads();

    const int warp = threadIdx.x >> 5, lane = threadIdx.x & 31;
    const int SPR = WOUT / (32 * WT);
    int seg = blockIdx.x * 8 + warp;
    int s   = seg % SPR;
    int row = seg / SPR;
    int h   = row % HOUT;
    int b   = row / HOUT;

    int wcol[WT];
#pragma unroll
    for (int k = 0; k < WT; k++) wcol[k] = s * 32 * WT + lane + 32 * k;

    unsigned long long acc[WT][COT / 2];
#pragma unroll
    for (int k = 0; k < WT; k++)
#pragma unroll
        for (int j = 0; j < COT / 2; j++)
            acc[k][j] = pk(bias[cob + 2 * j], bias[cob + 2 * j + 1]);

    const float* inb = in + (size_t)b * CI * HIN * WIN;
#pragma unroll 2
    for (int ci = 0; ci < CI; ci++) {
        const float* inp = inb + (size_t)ci * HIN * WIN;
#pragma unroll
        for (int kh = 0; kh < K; kh++) {
            int hi = h * ST - PD + kh;
            if ((unsigned)hi >= (unsigned)HIN) continue;
            const float* rp = inp + hi * WIN;
#pragma unroll
            for (int kw = 0; kw < K; kw++) {
                const ulonglong2* wv = reinterpret_cast<const ulonglong2*>(
                    ws + (ci * (K * K) + kh * K + kw) * COT);
                unsigned long long vv[WT];
#pragma unroll
                for (int k = 0; k < WT; k++) {
                    int wi = wcol[k] * ST - PD + kw;
                    float v = ((unsigned)wi < (unsigned)WIN) ? rp[wi] : 0.0f;
                    vv[k] = pk2(v);
                }
#pragma unroll
                for (int j = 0; j < COT / 4; j++) {
                    ulonglong2 w2 = wv[j];
#pragma unroll
                    for (int k = 0; k < WT; k++) {
                        fma2(acc[k][2 * j], vv[k], w2.x);
                        fma2(acc[k][2 * j + 1], vv[k], w2.y);
                    }
                }
            }
        }
    }

    size_t obase = ((size_t)b * CO + cob) * HOUT * WOUT + (size_t)h * WOUT;
#pragma unroll
    for (int k = 0; k < WT; k++)
#pragma unroll
        for (int j = 0; j < COT / 2; j++) {
            float2 r = up2(acc[k][j]);
            float v0 = r.x > 0.0f ? r.x : 0.0f;
            float v1 = r.y > 0.0f ? r.y : 0.0f;
            if (RND) { v0 = cvt_tf32(v0); v1 = cvt_tf32(v1); }
            out[obase + (size_t)(2 * j) * HOUT * WOUT + wcol[k]] = v0;
            out[obase + (size_t)(2 * j + 1) * HOUT * WOUT + wcol[k]] = v1;
        }
}

// ---------------- small-CO stride-1 conv + sigmoid (dc3), f32x2 spatial pairs ----------------
template<int CI, int K, int CO, int WT, int HIN, int WIN, int PD>
__global__ void conv_sig_k(const float* __restrict__ in, const float* __restrict__ wt,
                           const float* __restrict__ bias, float* __restrict__ out) {
    constexpr int HOUT = HIN, WOUT = WIN;
    extern __shared__ float ws[];
    for (int i = threadIdx.x; i < CI * K * K * CO; i += 256) ws[i] = wt[i];
    __syncthreads();

    const int warp = threadIdx.x >> 5, lane = threadIdx.x & 31;
    const int SPR = WOUT / (32 * WT);
    int seg = blockIdx.x * 8 + warp;
    int s   = seg % SPR;
    int row = seg / SPR;
    int h   = row % HOUT;
    int b   = row / HOUT;

    int wcol[WT];
#pragma unroll
    for (int k = 0; k < WT; k++) wcol[k] = s * 32 * WT + lane + 32 * k;

    unsigned long long acc[WT / 2][CO];
#pragma unroll
    for (int p = 0; p < WT / 2; p++)
#pragma unroll
        for (int c = 0; c < CO; c++) acc[p][c] = pk2(bias[c]);

    const float* inb = in + (size_t)b * CI * HIN * WIN;
#pragma unroll 2
    for (int ci = 0; ci < CI; ci++) {
        const float* inp = inb + (size_t)ci * HIN * WIN;
#pragma unroll
        for (int kh = 0; kh < K; kh++) {
            int hi = h - PD + kh;
            if ((unsigned)hi >= (unsigned)HIN) continue;
            const float* rp = inp + hi * WIN;
#pragma unroll
            for (int kw = 0; kw < K; kw++) {
                const float* wr = ws + (ci * (K * K) + kh * K + kw) * CO;
                float v[WT];
#pragma unroll
                for (int k = 0; k < WT; k++) {
                    int wi = wcol[k] - PD + kw;
                    v[k] = ((unsigned)wi < (unsigned)WIN) ? rp[wi] : 0.0f;
                }
#pragma unroll
                for (int c = 0; c < CO; c++) {
                    unsigned long long w2 = pk2(wr[c]);
#pragma unroll
                    for (int p = 0; p < WT / 2; p++)
                        fma2(acc[p][c], pk(v[2 * p], v[2 * p + 1]), w2);
                }
            }
        }
    }

    size_t obase = (size_t)b * CO * HOUT * WOUT + (size_t)h * WOUT;
#pragma unroll
    for (int p = 0; p < WT / 2; p++)
#pragma unroll
        for (int c = 0; c < CO; c++) {
            float2 r = up2(acc[p][c]);
            float v0 = 1.0f / (1.0f + __expf(-r.x));
            float v1 = 1.0f / (1.0f + __expf(-r.y));
            out[obase + (size_t)c * HOUT * WOUT + wcol[2 * p]] = v0;
            out[obase + (size_t)c * HOUT * WOUT + wcol[2 * p + 1]] = v1;
        }
}

// ---------------- vector quantize (z NCHW) -> indices + loss, pair-packed f32x2 ----------------
__global__ void vq_k(const float* __restrict__ emb, const float* __restrict__ z,
                     int* __restrict__ idx) {
    extern __shared__ float sm[];
    // paired codebook: float4 at (pair, j2) = {e[2k][2j2], e[2k+1][2j2], e[2k][2j2+1], e[2k+1][2j2+1]}
    float4* sp4 = (float4*)sm;               // 256*32 float4 = 131072 B
    float2* sn2 = (float2*)(sm + 512 * 64);  // 256 norm pairs
    for (int i = threadIdx.x; i < 512 * 64; i += blockDim.x) {
        int k = i >> 6, j = i & 63;
        int dst = ((k >> 1) * 32 + (j >> 1)) * 4 + (j & 1) * 2 + (k & 1);
        sm[dst] = emb[i];
    }
    __syncthreads();
    for (int kp = threadIdx.x; kp < 256; kp += blockDim.x) {
        float sx = 0.0f, sy = 0.0f;
#pragma unroll
        for (int j2 = 0; j2 < 32; j2++) {
            float4 e = sp4[kp * 32 + j2];
            sx += e.x * e.x + e.z * e.z;
            sy += e.y * e.y + e.w * e.w;
        }
        sn2[kp] = make_float2(sx, sy);
    }
    __syncthreads();

    int n = blockIdx.x * blockDim.x + threadIdx.x;
    int b  = n >> 12;
    int hw = n & 4095;
    const float* zp = z + (size_t)b * 262144 + hw;
    float zr[64];
#pragma unroll
    for (int j = 0; j < 64; j++) zr[j] = zp[(size_t)j * 4096];

    float best = 3.4e38f;
    int bi = 0;
    for (int kp = 0; kp < 256; kp++) {
        const float4* ep = sp4 + kp * 32;
        unsigned long long dp = pk(0.0f, 0.0f);
#pragma unroll
        for (int j2 = 0; j2 < 32; j2++) {
            float4 e = ep[j2];
            fma2(dp, pk2(zr[2 * j2]),     pk(e.x, e.y));
            fma2(dp, pk2(zr[2 * j2 + 1]), pk(e.z, e.w));
        }
        float2 d2 = up2(dp);
        float2 nn = sn2[kp];
        float dx = nn.x - 2.0f * d2.x;
        if (dx < best) { best = dx; bi = 2 * kp; }
        float dy = nn.y - 2.0f * d2.y;
        if (dy < best) { best = dy; bi = 2 * kp + 1; }
    }

    idx[n] = bi;
    float ls = 0.0f;
#pragma unroll
    for (int j = 0; j < 64; j++) {
        float e = sm[((bi >> 1) * 32 + (j >> 1)) * 4 + (j & 1) * 2 + (bi & 1)];
        float df = e - zr[j];
        ls += df * df;
    }
#pragma unroll
    for (int o = 16; o > 0; o >>= 1) ls += __shfl_xor_sync(0xffffffffu, ls, o);
    if ((threadIdx.x & 31) == 0) atomicAdd(&g_loss, ls);
}

// materialize q in NCHW, coalesced, tf32-rounded (feeds dc1 mma)
__global__ void gather_q_k(const float* __restrict__ emb, const int* __restrict__ idx,
                           float* __restrict__ q) {
    int i = blockIdx.x * blockDim.x + threadIdx.x;
    int hw = i & 4095;
    int t  = i >> 12;
    int c  = t & 63;
    int b  = t >> 6;
    q[i] = cvt_tf32(emb[idx[(b << 12) + hw] * 64 + c]);
}

// ---------------- host ----------------
static float* sym_addr(const void* sym) {
    void* p = nullptr;
    cudaGetSymbolAddress(&p, sym);
    return (float*)p;
}

extern "C" void kernel_launch(void* const* d_in, const int* in_sizes, int n_in,
                              void* d_out, int out_size) {
    const float* x   = (const float*)d_in[0];
    const float* w1  = (const float*)d_in[1];
    const float* b1  = (const float*)d_in[2];
    const float* w2  = (const float*)d_in[3];
    const float* b2  = (const float*)d_in[4];
    const float* w3  = (const float*)d_in[5];
    const float* b3  = (const float*)d_in[6];
    const float* emb = (const float*)d_in[7];
    const float* dw1 = (const float*)d_in[8];
    const float* db1 = (const float*)d_in[9];
    const float* dw2 = (const float*)d_in[10];
    const float* db2 = (const float*)d_in[11];
    const float* dw3 = (const float*)d_in[12];
    const float* db3 = (const float*)d_in[13];
    float* out = (float*)d_out;

    float*  h1   = sym_addr(g_h1);
    float*  h2   = sym_addr(g_h2);
    float*  z    = sym_addr(g_z);
    float*  q    = sym_addr(g_q);
    float*  d1   = sym_addr(g_d1);
    float*  d2   = sym_addr(g_d2);
    float*  wt1  = sym_addr(g_wt1);
    float*  wt3d = sym_addr(g_wt3d);
    float2* pw1f = (float2*)sym_addr(g_pw1f);
    float2* pw2f = (float2*)sym_addr(g_pw2f);
    float2* cw2f = (float2*)sym_addr(g_cw2f);
    float2* cw3f = (float2*)sym_addr(g_cw3f);
    int*    idx  = (int*)sym_addr(g_idx);

    auto c1  = conv_f2_k<3, 4, 64, 32, 2, 256, 256, 128, 128, 2, 1, true>;
    auto c2m = conv2_mma_k<64, 128, 128, 128, 4, true>;
    auto c3m = conv3_mma_k<128, 64, 64, 8>;
    auto dc1 = deconv_mma_k<64, 128, 2, 64, 80, 64, 64, 8, true>;
    auto dc2 = deconv_mma_k<128, 64, 1, 128, 144, 128, 128, 8, false>;
    auto dc3 = conv_sig_k<64, 3, 3, 4, 256, 256, 1>;

    // smem sizes
    const int smem_c2  = 2 * (4 * 6 * 130) * 4 + 2 * (4 * 2 * 16 * 32) * 8;  // 90496
    const int smem_c3  = 2 * (8 * 4 * 80) * 4 + 2 * (4 * 3 * 8 * 32) * 8;    // 69632
    const int smem_dc1 = 2 * (8 * 3 * 80) * 4 + 2 * (4 * 16 * 32) * 8;       // 48128
    const int smem_dc2 = 2 * (8 * 2 * 144) * 4 + 2 * (4 * 8 * 32) * 8;       // 34816
    const int smem_vq  = 512 * 64 * 4 + 256 * 8;                             // 133120

    cudaFuncSetAttribute(c2m, cudaFuncAttributeMaxDynamicSharedMemorySize, smem_c2);
    cudaFuncSetAttribute(c3m, cudaFuncAttributeMaxDynamicSharedMemorySize, smem_c3);
    cudaFuncSetAttribute(dc1, cudaFuncAttributeMaxDynamicSharedMemorySize, smem_dc1);
    cudaFuncSetAttribute(dc2, cudaFuncAttributeMaxDynamicSharedMemorySize, smem_dc2);
    cudaFuncSetAttribute(vq_k, cudaFuncAttributeMaxDynamicSharedMemorySize, smem_vq);

    // repack weights
    repack_conv<<<(64 * 3 * 16 + 255) / 256, 256>>>(w1, wt1, 64, 3, 16);
    repack_c2_frag<<<(64 * 2 * 16 * 32) / 256, 256>>>(w2, cw2f, 64, 128, 16);
    repack_c3_frag<<<(64 * 3 * 8 * 32) / 256, 256>>>(w3, cw3f, 128, 64, 8);
    repack_par_frag<<<(4 * 32 * 16 * 32) / 256, 256>>>(dw1, pw1f, 64, 128, 16);
    repack_par_frag<<<(4 * 64 * 8 * 32) / 256, 256>>>(dw2, pw2f, 128, 64, 8);
    repack_deconv_flip<<<(64 * 3 * 9 + 255) / 256, 256>>>(dw3, wt3d, 3, 64, 3);
    zero_loss_k<<<1, 1>>>();

    // encoder
    c1<<<dim3(1024, 2), 256, 3 * 16 * 32 * 4>>>(x, wt1, b1, h1);
    c2m<<<dim3(32 * 32), 256, smem_c2>>>(h1, cw2f, b2, h2);
    c3m<<<dim3(32 * 32), 256, smem_c3>>>(h2, cw3f, b3, z);

    // vector quantize
    vq_k<<<512, 256, smem_vq>>>(emb, z, idx);
    gather_q_k<<<(32 * 64 * 4096) / 256, 256>>>(emb, idx, q);

    // decoder
    dc1<<<dim3(32 * 32, 1, 4), 256, smem_dc1>>>(q, pw1f, db1, d1);
    dc2<<<dim3(128 * 32, 1, 4), 256, smem_dc2>>>(d1, pw2f, db2, d2);
    dc3<<<dim3(2048, 1), 256, 64 * 9 * 3 * 4>>>(d2, wt3d, db3, out);

    finalize_k<<<1, 1>>>(out, out_size - 1);
}

// round 7
// speedup vs baseline: 14.9098x; 1.0168x over previous
#include <cuda_runtime.h>
#include <math.h>

// ---------------- scratch (device globals: allocation-free rule) ----------------
__device__ float g_h1[32u * 64 * 128 * 128];   // after conv1+relu   (NCHW, tf32-rounded)
__device__ float g_h2[32u * 128 * 64 * 64];    // after conv2+relu   (NCHW, tf32-rounded)
__device__ float g_z [32u * 64 * 64 * 64];     // after conv3+relu   (NCHW, fp32)
__device__ float g_q [32u * 64 * 64 * 64];     // quantized          (NCHW, tf32-rounded)
__device__ float g_d1[32u * 128 * 128 * 128];  // after deconv1+relu (NCHW, tf32-rounded)
__device__ float g_d2[32u * 64 * 256 * 256];   // after deconv2+relu (NCHW, fp32)

// repacked weights
__device__ float  g_wt1 [64 * 3 * 16];          // c1 scalar path
__device__ float  g_wt3d[3 * 64 * 9];           // dc3 flipped -> plain conv
__device__ float2 g_pw1f[4 * 32 * 16 * 32];     // dc1 B, mma-fragment order
__device__ float2 g_pw2f[4 * 64 * 8 * 32];      // dc2 B, fragment order
__device__ float2 g_cw2f[128 * 16 * 32];        // c2  B, fragment order
__device__ float2 g_cw3f[64 * 3 * 8 * 32];      // c3  B, fragment order (12 taps, kw=3 zeroed)

__device__ float g_loss;

// ---------------- helpers ----------------
__device__ __forceinline__ float cvt_tf32(float x) {
    asm("cvt.rna.tf32.f32 %0, %0;" : "+f"(x));
    return x;
}
__device__ __forceinline__ unsigned long long pk2(float x) {
    unsigned long long r;
    asm("mov.b64 %0, {%1, %1};" : "=l"(r) : "f"(x));
    return r;
}
__device__ __forceinline__ unsigned long long pk(float x, float y) {
    unsigned long long r;
    asm("mov.b64 %0, {%1, %2};" : "=l"(r) : "f"(x), "f"(y));
    return r;
}
__device__ __forceinline__ void fma2(unsigned long long& d,
                                     unsigned long long a, unsigned long long b) {
    asm("fma.rn.f32x2 %0, %1, %2, %0;" : "+l"(d) : "l"(a), "l"(b));
}
__device__ __forceinline__ float2 up2(unsigned long long v) {
    float2 f;
    asm("mov.b64 {%0, %1}, %2;" : "=f"(f.x), "=f"(f.y) : "l"(v));
    return f;
}
__device__ __forceinline__ void mma_tf32(float* c, unsigned a0, unsigned a1,
                                         unsigned a2, unsigned a3,
                                         unsigned b0, unsigned b1) {
    asm volatile(
        "mma.sync.aligned.m16n8k8.row.col.f32.tf32.tf32.f32 "
        "{%0,%1,%2,%3}, {%4,%5,%6,%7}, {%8,%9}, {%0,%1,%2,%3};"
        : "+f"(c[0]), "+f"(c[1]), "+f"(c[2]), "+f"(c[3])
        : "r"(a0), "r"(a1), "r"(a2), "r"(a3), "r"(b0), "r"(b1));
}
__device__ __forceinline__ unsigned smem_u32(const void* p) {
    return (unsigned)__cvta_generic_to_shared(p);
}
__device__ __forceinline__ void cp_async4(unsigned dst, const void* src, bool pred) {
    int sz = pred ? 4 : 0;
    asm volatile("cp.async.ca.shared.global [%0], [%1], 4, %2;"
                 :: "r"(dst), "l"(src), "r"(sz));
}
__device__ __forceinline__ void cp_async16(unsigned dst, const void* src) {
    asm volatile("cp.async.cg.shared.global [%0], [%1], 16;" :: "r"(dst), "l"(src));
}
__device__ __forceinline__ void cp_commit() {
    asm volatile("cp.async.commit_group;");
}
template<int N> __device__ __forceinline__ void cp_wait() {
    asm volatile("cp.async.wait_group %0;" :: "n"(N));
}

// ---------------- fused weight repack (single launch; also zeroes loss) ----------------
__global__ void repack_all_k(const float* __restrict__ w1, const float* __restrict__ w2,
                             const float* __restrict__ w3, const float* __restrict__ dw1,
                             const float* __restrict__ dw2, const float* __restrict__ dw3,
                             float* __restrict__ wt1, float2* __restrict__ cw2f,
                             float2* __restrict__ cw3f, float2* __restrict__ pw1f,
                             float2* __restrict__ pw2f, float* __restrict__ wt3d) {
    int i = blockIdx.x * blockDim.x + threadIdx.x;
    if (i == 0) g_loss = 0.0f;

    // seg 0: c1 weights [(ci*16+t)*64+co], Co=64 Ci=3 KK=16, total 3072
    if (i < 3072) {
        int co = i / 48, r = i % 48;
        wt1[r * 64 + co] = w1[i];
        return;
    }
    i -= 3072;
    // seg 1: c2 B fragment order, CI=64 CO=128 NT=16, total 65536
    if (i < 65536) {
        int lane = i & 31;
        int t1 = i >> 5;
        int nt = t1 % 16;
        int s  = t1 / 16;
        int ci = s >> 1, th = s & 1;
        int kw = lane & 3;
        int co = nt * 8 + (lane >> 2);
        float v0 = w2[((co * 64 + ci) * 4 + 2 * th) * 4 + kw];
        float v1 = w2[((co * 64 + ci) * 4 + 2 * th + 1) * 4 + kw];
        cw2f[i] = make_float2(cvt_tf32(v0), cvt_tf32(v1));
        return;
    }
    i -= 65536;
    // seg 2: c3 B fragment order, CI=128 CO=64 NT=8, total 49152
    if (i < 49152) {
        int lane = i & 31;
        int t1 = i >> 5;
        int nt = t1 % 8;
        int t2 = t1 / 8;
        int g  = t2 % 3;
        int s  = t2 / 3;
        int kw = lane & 3;
        int co = nt * 8 + (lane >> 2);
        float v0 = 0.0f, v1 = 0.0f;
        if (kw < 3) {
            v0 = w3[((co * 128 + 2 * s) * 3 + g) * 3 + kw];
            v1 = w3[((co * 128 + 2 * s + 1) * 3 + g) * 3 + kw];
        }
        cw3f[i] = make_float2(cvt_tf32(v0), cvt_tf32(v1));
        return;
    }
    i -= 49152;
    // seg 3: dc1 B parity-fragment order, CI=64 CO=128 NT=16, total 65536
    if (i < 65536) {
        int lane = i & 31;
        int t1 = i >> 5;
        int nt = t1 % 16;
        int t2 = t1 / 16;
        int s  = t2 % 32;
        int p  = t2 / 32;
        int tap = lane & 3;
        int a = tap >> 1, bt = tap & 1;
        int ph = p >> 1, pwb = p & 1;
        int kh = ph ? (a ? 0 : 2) : (a ? 3 : 1);
        int kw = pwb ? (bt ? 0 : 2) : (bt ? 3 : 1);
        int co = nt * 8 + (lane >> 2);
        float v0 = dw1[(((2 * s) * 128 + co) * 4 + kh) * 4 + kw];
        float v1 = dw1[(((2 * s + 1) * 128 + co) * 4 + kh) * 4 + kw];
        pw1f[i] = make_float2(cvt_tf32(v0), cvt_tf32(v1));
        return;
    }
    i -= 65536;
    // seg 4: dc2 B parity-fragment order, CI=128 CO=64 NT=8, total 32768
    if (i < 32768) {
        int lane = i & 31;
        int t1 = i >> 5;
        int nt = t1 % 8;
        int t2 = t1 / 8;
        int s  = t2 % 64;
        int p  = t2 / 64;
        int tap = lane & 3;
        int a = tap >> 1, bt = tap & 1;
        int ph = p >> 1, pwb = p & 1;
        int kh = ph ? (a ? 0 : 2) : (a ? 3 : 1);
        int kw = pwb ? (bt ? 0 : 2) : (bt ? 3 : 1);
        int co = nt * 8 + (lane >> 2);
        float v0 = dw2[(((2 * s) * 64 + co) * 4 + kh) * 4 + kw];
        float v1 = dw2[(((2 * s + 1) * 64 + co) * 4 + kh) * 4 + kw];
        pw2f[i] = make_float2(cvt_tf32(v0), cvt_tf32(v1));
        return;
    }
    i -= 32768;
    // seg 5: dc3 flip -> plain conv [(ci*9+tf)*3+co], Ci=64 Co=3 K=3, total 1728
    if (i < 1728) {
        int ci = i / 27;
        int r  = i % 27;
        int co = r / 9;
        int t  = r % 9;
        int kh = t / 3, kw = t % 3;
        int tf = (2 - kh) * 3 + (2 - kw);
        wt3d[(ci * 9 + tf) * 3 + co] = dw3[i];
    }
}

__global__ void finalize_k(float* __restrict__ out, int loss_idx) {
    out[loss_idx] = 1.25f * g_loss * (1.0f / 8388608.0f);
}

// ================= MMA stride-2 deconv, parity-decomposed, pipelined =================
// blockIdx.x = parity (fastest-varying -> 4 parity blocks of a tile are wave-adjacent,
// so their shared input tile stays L2-hot). blockIdx.y = spatial/batch tile.
template<int CI, int CO, int MH, int MW, int MWP, int HIN, int WIN, int KC, bool RND>
__global__ void deconv_mma_k(const float* __restrict__ in, const float2* __restrict__ wf,
                             const float* __restrict__ bias, float* __restrict__ out) {
    constexpr int R = MH + 1;
    constexpr int NT = CO / 8;
    constexpr int PLANE = R * MWP;
    constexpr int ASZ = KC * PLANE;
    constexpr int BSZ = (KC / 2) * NT * 32;
    constexpr int NC = CI / KC;
    constexpr int HOUT = 2 * HIN, WOUT = 2 * WIN;
    extern __shared__ float sm[];
    float*  sA = sm;
    float2* sB = (float2*)(sm + 2 * ASZ);

    const int p  = blockIdx.x, ph = p >> 1, pw = p & 1;
    const int tiles_h = HIN / MH;
    const int h0 = (blockIdx.y % tiles_h) * MH;
    const int b  = blockIdx.y / tiles_h;
    const int warp = threadIdx.x >> 5, lane = threadIdx.x & 31;
    const int tap = lane & 3;
    const int a = tap >> 1, bt = tap & 1;
    const int roff = ph ? a : 1 - a;
    const int coff = pw ? bt : 1 - bt;
    const int mbase = warp * 16;
    const int mr = mbase / MW;
    const int colq = (mbase % MW) + 2 * (lane >> 2);
    const int aoff0 = (mr + roff) * MWP + colq + coff;

    float acc[NT][4];
#pragma unroll
    for (int nt = 0; nt < NT; nt++) {
        float b0v = bias[nt * 8 + 2 * (lane & 3)];
        float b1v = bias[nt * 8 + 2 * (lane & 3) + 1];
        acc[nt][0] = b0v; acc[nt][1] = b1v; acc[nt][2] = b0v; acc[nt][3] = b1v;
    }

    const float*  inb = in + (size_t)b * CI * HIN * WIN;
    const float2* wpb = wf + (size_t)p * (CI / 2) * NT * 32;
    const unsigned sAu = smem_u32(sA);
    const unsigned sBu = smem_u32(sB);

    auto stageA = [&](int ci0, int buf) {
        for (int i = threadIdx.x; i < ASZ; i += 256) {
            int ci_l = i / PLANE;
            int rem  = i % PLANE;
            int r = rem / MWP, c = rem % MWP;
            int gr = h0 + r - (ph ? 0 : 1);
            int gc = c - (pw ? 0 : 1);
            bool ok = (unsigned)gr < (unsigned)HIN && (unsigned)gc < (unsigned)WIN;
            const float* src = inb + (size_t)(ci0 + ci_l) * HIN * WIN
                               + (ok ? gr * WIN + gc : 0);
            cp_async4(sAu + (buf * ASZ + i) * 4, src, ok);
        }
    };
    auto stageB = [&](int ci0, int buf) {
        const char* src = (const char*)(wpb + (size_t)(ci0 / 2) * NT * 32);
        for (int i = threadIdx.x; i < BSZ / 2; i += 256)
            cp_async16(sBu + buf * BSZ * 8 + i * 16, src + i * 16);
    };

    stageA(0, 0); stageB(0, 0); cp_commit();
    for (int c = 0; c < NC; c++) {
        int buf = c & 1;
        if (c + 1 < NC) {
            stageA((c + 1) * KC, buf ^ 1);
            stageB((c + 1) * KC, buf ^ 1);
            cp_commit();
            cp_wait<1>();
        } else {
            cp_wait<0>();
        }
        __syncthreads();
        const float*  bA = sA + buf * ASZ;
        const float2* bB = sB + buf * BSZ;
#pragma unroll
        for (int s = 0; s < KC / 2; s++) {
            const float* pa = bA + 2 * s * PLANE + aoff0;
            unsigned a0 = __float_as_uint(pa[0]);
            unsigned a1 = __float_as_uint(pa[1]);
            unsigned a2 = __float_as_uint(pa[PLANE]);
            unsigned a3 = __float_as_uint(pa[PLANE + 1]);
            const float2* pb = bB + s * NT * 32 + lane;
#pragma unroll
            for (int nt = 0; nt < NT; nt++) {
                float2 bb = pb[nt * 32];
                mma_tf32(acc[nt], a0, a1, a2, a3,
                         __float_as_uint(bb.x), __float_as_uint(bb.y));
            }
        }
        __syncthreads();
    }

    const int ho = 2 * (h0 + mr) + ph;
#pragma unroll
    for (int nt = 0; nt < NT; nt++) {
        int n0 = nt * 8 + 2 * (lane & 3);
#pragma unroll
        for (int j = 0; j < 4; j++) {
            int n  = n0 + (j & 1);
            int wi = colq + (j >> 1);
            int wo = 2 * wi + pw;
            float v = acc[nt][j];
            v = v > 0.0f ? v : 0.0f;
            if (RND) v = cvt_tf32(v);
            out[((size_t)(b * CO + n) * HOUT + ho) * WOUT + wo] = v;
        }
    }
}

// ================= MMA conv2 4x4 stride-2, pipelined =================
template<int CI, int CO, int HIN, int WIN, int KC, bool RND>
__global__ void conv2_mma_k(const float* __restrict__ in, const float2* __restrict__ wf,
                            const float* __restrict__ bias, float* __restrict__ out) {
    constexpr int MH = 2, MW = 64;
    constexpr int R = 6, MWP = 2 * MW + 2;
    constexpr int NT = CO / 8;
    constexpr int PLANE = R * MWP;
    constexpr int ASZ = KC * PLANE;
    constexpr int BSZ = KC * 2 * NT * 32;
    constexpr int NC = CI / KC;
    constexpr int HOUT = HIN / 2, WOUT = WIN / 2;
    extern __shared__ float sm[];
    float*  sA = sm;
    float2* sB = (float2*)(sm + 2 * ASZ);

    const int tiles_h = HOUT / MH;
    const int h0 = (blockIdx.x % tiles_h) * MH;
    const int b  = blockIdx.x / tiles_h;
    const int warp = threadIdx.x >> 5, lane = threadIdx.x & 31;
    const int kw = lane & 3;
    const int mbase = warp * 16;
    const int mr = mbase / MW;
    const int colq = (mbase % MW) + 2 * (lane >> 2);

    float acc[NT][4];
#pragma unroll
    for (int nt = 0; nt < NT; nt++) {
        float b0v = bias[nt * 8 + 2 * (lane & 3)];
        float b1v = bias[nt * 8 + 2 * (lane & 3) + 1];
        acc[nt][0] = b0v; acc[nt][1] = b1v; acc[nt][2] = b0v; acc[nt][3] = b1v;
    }

    const float* inb = in + (size_t)b * CI * HIN * WIN;
    const unsigned sAu = smem_u32(sA);
    const unsigned sBu = smem_u32(sB);

    auto stageA = [&](int ci0, int buf) {
        for (int i = threadIdx.x; i < ASZ; i += 256) {
            int ci_l = i / PLANE;
            int rem  = i % PLANE;
            int r = rem / MWP, c = rem % MWP;
            int gr = 2 * h0 + r - 1;
            int gc = c - 1;
            bool ok = (unsigned)gr < (unsigned)HIN && (unsigned)gc < (unsigned)WIN;
            const float* src = inb + (size_t)(ci0 + ci_l) * HIN * WIN
                               + (ok ? gr * WIN + gc : 0);
            cp_async4(sAu + (buf * ASZ + i) * 4, src, ok);
        }
    };
    auto stageB = [&](int ci0, int buf) {
        const char* src = (const char*)(wf + (size_t)(ci0 * 2) * NT * 32);
        for (int i = threadIdx.x; i < BSZ / 2; i += 256)
            cp_async16(sBu + buf * BSZ * 8 + i * 16, src + i * 16);
    };

    stageA(0, 0); stageB(0, 0); cp_commit();
    for (int c = 0; c < NC; c++) {
        int buf = c & 1;
        if (c + 1 < NC) {
            stageA((c + 1) * KC, buf ^ 1);
            stageB((c + 1) * KC, buf ^ 1);
            cp_commit();
            cp_wait<1>();
        } else {
            cp_wait<0>();
        }
        __syncthreads();
        const float*  bA = sA + buf * ASZ;
        const float2* bB = sB + buf * BSZ;
#pragma unroll
        for (int s = 0; s < 2 * KC; s++) {
            int ci_l = s >> 1, th = s & 1;
            const float* pa = bA + ci_l * PLANE + (2 * mr + 2 * th) * MWP
                              + 2 * colq + kw;
            unsigned a0 = __float_as_uint(pa[0]);
            unsigned a1 = __float_as_uint(pa[2]);
            unsigned a2 = __float_as_uint(pa[MWP]);
            unsigned a3 = __float_as_uint(pa[MWP + 2]);
            const float2* pb = bB + s * NT * 32 + lane;
#pragma unroll
            for (int nt = 0; nt < NT; nt++) {
                float2 bb = pb[nt * 32];
                mma_tf32(acc[nt], a0, a1, a2, a3,
                         __float_as_uint(bb.x), __float_as_uint(bb.y));
            }
        }
        __syncthreads();
    }

    const int ho = h0 + mr;
#pragma unroll
    for (int nt = 0; nt < NT; nt++) {
        int n0 = nt * 8 + 2 * (lane & 3);
#pragma unroll
        for (int j = 0; j < 4; j++) {
            int n  = n0 + (j & 1);
            int wo = colq + (j >> 1);
            float v = acc[nt][j];
            v = v > 0.0f ? v : 0.0f;
            if (RND) v = cvt_tf32(v);
            out[((size_t)(b * CO + n) * HOUT + ho) * WOUT + wo] = v;
        }
    }
}

// ================= MMA conv3x3 stride-1 (c3), taps padded to 12, pipelined =================
template<int CI, int CO, int HW, int KC>
__global__ void conv3_mma_k(const float* __restrict__ in, const float2* __restrict__ wf,
                            const float* __restrict__ bias, float* __restrict__ out) {
    constexpr int MH = 2, MW = 64;
    constexpr int R = MH + 2;
    constexpr int MWP = 80;
    constexpr int NT = CO / 8;
    constexpr int PLANE = R * MWP;
    constexpr int ASZ = KC * PLANE;
    constexpr int BSZ = (KC / 2) * 3 * NT * 32;
    constexpr int NC = CI / KC;
    extern __shared__ float sm[];
    float*  sA = sm;
    float2* sB = (float2*)(sm + 2 * ASZ);

    const int tiles_h = HW / MH;
    const int h0 = (blockIdx.x % tiles_h) * MH;
    const int b  = blockIdx.x / tiles_h;
    const int warp = threadIdx.x >> 5, lane = threadIdx.x & 31;
    const int mbase = warp * 16;
    const int mr = mbase / MW;
    const int colq = (mbase % MW) + 2 * (lane >> 2);

    float acc[NT][4];
#pragma unroll
    for (int nt = 0; nt < NT; nt++) {
        float b0v = bias[nt * 8 + 2 * (lane & 3)];
        float b1v = bias[nt * 8 + 2 * (lane & 3) + 1];
        acc[nt][0] = b0v; acc[nt][1] = b1v; acc[nt][2] = b0v; acc[nt][3] = b1v;
    }

    const float* inb = in + (size_t)b * CI * HW * HW;
    const unsigned sAu = smem_u32(sA);
    const unsigned sBu = smem_u32(sB);

    auto stageA = [&](int ci0, int buf) {
        for (int i = threadIdx.x; i < ASZ; i += 256) {
            int ci_l = i / PLANE;
            int rem  = i % PLANE;
            int r = rem / MWP, c = rem % MWP;
            int gr = h0 + r - 1;
            int gc = c - 1;
            bool ok = (unsigned)gr < (unsigned)HW && (unsigned)gc < (unsigned)HW;
            const float* src = inb + (size_t)(ci0 + ci_l) * HW * HW
                               + (ok ? gr * HW + gc : 0);
            cp_async4(sAu + (buf * ASZ + i) * 4, src, ok);
        }
    };
    auto stageB = [&](int ci0, int buf) {
        const char* src = (const char*)(wf + (size_t)(ci0 / 2) * 3 * NT * 32);
        for (int i = threadIdx.x; i < BSZ / 2; i += 256)
            cp_async16(sBu + buf * BSZ * 8 + i * 16, src + i * 16);
    };

    stageA(0, 0); stageB(0, 0); cp_commit();
    for (int c = 0; c < NC; c++) {
        int buf = c & 1;
        if (c + 1 < NC) {
            stageA((c + 1) * KC, buf ^ 1);
            stageB((c + 1) * KC, buf ^ 1);
            cp_commit();
            cp_wait<1>();
        } else {
            cp_wait<0>();
        }
        __syncthreads();
        const float*  bA = sA + buf * ASZ;
        const float2* bB = sB + buf * BSZ;
#pragma unroll
        for (int s = 0; s < KC / 2; s++) {
#pragma unroll
            for (int g = 0; g < 3; g++) {
                const float* pa = bA + 2 * s * PLANE + (mr + g) * MWP
                                  + colq + (lane & 3);
                unsigned a0 = __float_as_uint(pa[0]);
                unsigned a1 = __float_as_uint(pa[1]);
                unsigned a2 = __float_as_uint(pa[PLANE]);
                unsigned a3 = __float_as_uint(pa[PLANE + 1]);
                const float2* pb = bB + (s * 3 + g) * NT * 32 + lane;
#pragma unroll
                for (int nt = 0; nt < NT; nt++) {
                    float2 bb = pb[nt * 32];
                    mma_tf32(acc[nt], a0, a1, a2, a3,
                             __float_as_uint(bb.x), __float_as_uint(bb.y));
                }
            }
        }
        __syncthreads();
    }

    const int ho = h0 + mr;
#pragma unroll
    for (int nt = 0; nt < NT; nt++) {
        int n0 = nt * 8 + 2 * (lane & 3);
#pragma unroll
        for (int j = 0; j < 4; j++) {
            int n  = n0 + (j & 1);
            int wo = colq + (j >> 1);
            float v = acc[nt][j];
            v = v > 0.0f ? v : 0.0f;
            out[((size_t)(b * CO + n) * HW + ho) * HW + wo] = v;
        }
    }
}

// ---------------- conv + relu, f32x2 (c1) ----------------
template<int CI, int K, int CO, int COT, int WT,
         int HIN, int WIN, int HOUT, int WOUT, int ST, int PD, bool RND>
__global__ void conv_f2_k(const float* __restrict__ in, const float* __restrict__ wt,
                          const float* __restrict__ bias, float* __restrict__ out) {
    extern __shared__ float ws[];
    const int cob = blockIdx.y * COT;
    const int WROWS = CI * K * K;
    for (int i = threadIdx.x; i < WROWS * COT; i += 256) {
        int r = i / COT, c = i % COT;
        ws[i] = wt[r * CO + cob + c];
    }
    __syncthreads();

    const int warp = threadIdx.x >> 5, lane = threadIdx.x & 31;
    const int SPR = WOUT / (32 * WT);
    int seg = blockIdx.x * 8 + warp;
    int s   = seg % SPR;
    int row = seg / SPR;
    int h   = row % HOUT;
    int b   = row / HOUT;

    int wcol[WT];
#pragma unroll
    for (int k = 0; k < WT; k++) wcol[k] = s * 32 * WT + lane + 32 * k;

    unsigned long long acc[WT][COT / 2];
#pragma unroll
    for (int k = 0; k < WT; k++)
#pragma unroll
        for (int j = 0; j < COT / 2; j++)
            acc[k][j] = pk(bias[cob + 2 * j], bias[cob + 2 * j + 1]);

    const float* inb = in + (size_t)b * CI * HIN * WIN;
#pragma unroll 2
    for (int ci = 0; ci < CI; ci++) {
        const float* inp = inb + (size_t)ci * HIN * WIN;
#pragma unroll
        for (int kh = 0; kh < K; kh++) {
            int hi = h * ST - PD + kh;
            if ((unsigned)hi >= (unsigned)HIN) continue;
            const float* rp = inp + hi * WIN;
#pragma unroll
            for (int kw = 0; kw < K; kw++) {
                const ulonglong2* wv = reinterpret_cast<const ulonglong2*>(
                    ws + (ci * (K * K) + kh * K + kw) * COT);
                unsigned long long vv[WT];
#pragma unroll
                for (int k = 0; k < WT; k++) {
                    int wi = wcol[k] * ST - PD + kw;
                    float v = ((unsigned)wi < (unsigned)WIN) ? rp[wi] : 0.0f;
                    vv[k] = pk2(v);
                }
#pragma unroll
                for (int j = 0; j < COT / 4; j++) {
                    ulonglong2 w2 = wv[j];
#pragma unroll
                    for (int k = 0; k < WT; k++) {
                        fma2(acc[k][2 * j], vv[k], w2.x);
                        fma2(acc[k][2 * j + 1], vv[k], w2.y);
                    }
                }
            }
        }
    }

    size_t obase = ((size_t)b * CO + cob) * HOUT * WOUT + (size_t)h * WOUT;
#pragma unroll
    for (int k = 0; k < WT; k++)
#pragma unroll
        for (int j = 0; j < COT / 2; j++) {
            float2 r = up2(acc[k][j]);
            float v0 = r.x > 0.0f ? r.x : 0.0f;
            float v1 = r.y > 0.0f ? r.y : 0.0f;
            if (RND) { v0 = cvt_tf32(v0); v1 = cvt_tf32(v1); }
            out[obase + (size_t)(2 * j) * HOUT * WOUT + wcol[k]] = v0;
            out[obase + (size_t)(2 * j + 1) * HOUT * WOUT + wcol[k]] = v1;
        }
}

// ---------------- small-CO stride-1 conv + sigmoid (dc3), f32x2 spatial pairs ----------------
template<int CI, int K, int CO, int WT, int HIN, int WIN, int PD>
__global__ void conv_sig_k(const float* __restrict__ in, const float* __restrict__ wt,
                           const float* __restrict__ bias, float* __restrict__ out) {
    constexpr int HOUT = HIN, WOUT = WIN;
    extern __shared__ float ws[];
    for (int i = threadIdx.x; i < CI * K * K * CO; i += 256) ws[i] = wt[i];
    __syncthreads();

    const int warp = threadIdx.x >> 5, lane = threadIdx.x & 31;
    const int SPR = WOUT / (32 * WT);
    int seg = blockIdx.x * 8 + warp;
    int s   = seg % SPR;
    int row = seg / SPR;
    int h   = row % HOUT;
    int b   = row / HOUT;

    int wcol[WT];
#pragma unroll
    for (int k = 0; k < WT; k++) wcol[k] = s * 32 * WT + lane + 32 * k;

    unsigned long long acc[WT / 2][CO];
#pragma unroll
    for (int p = 0; p < WT / 2; p++)
#pragma unroll
        for (int c = 0; c < CO; c++) acc[p][c] = pk2(bias[c]);

    const float* inb = in + (size_t)b * CI * HIN * WIN;
#pragma unroll 2
    for (int ci = 0; ci < CI; ci++) {
        const float* inp = inb + (size_t)ci * HIN * WIN;
#pragma unroll
        for (int kh = 0; kh < K; kh++) {
            int hi = h - PD + kh;
            if ((unsigned)hi >= (unsigned)HIN) continue;
            const float* rp = inp + hi * WIN;
#pragma unroll
            for (int kw = 0; kw < K; kw++) {
                const float* wr = ws + (ci * (K * K) + kh * K + kw) * CO;
                float v[WT];
#pragma unroll
                for (int k = 0; k < WT; k++) {
                    int wi = wcol[k] - PD + kw;
                    v[k] = ((unsigned)wi < (unsigned)WIN) ? rp[wi] : 0.0f;
                }
#pragma unroll
                for (int c = 0; c < CO; c++) {
                    unsigned long long w2 = pk2(wr[c]);
#pragma unroll
                    for (int p = 0; p < WT / 2; p++)
                        fma2(acc[p][c], pk(v[2 * p], v[2 * p + 1]), w2);
                }
            }
        }
    }

    size_t obase = (size_t)b * CO * HOUT * WOUT + (size_t)h * WOUT;
#pragma unroll
    for (int p = 0; p < WT / 2; p++)
#pragma unroll
        for (int c = 0; c < CO; c++) {
            float2 r = up2(acc[p][c]);
            float v0 = 1.0f / (1.0f + __expf(-r.x));
            float v1 = 1.0f / (1.0f + __expf(-r.y));
            out[obase + (size_t)c * HOUT * WOUT + wcol[2 * p]] = v0;
            out[obase + (size_t)c * HOUT * WOUT + wcol[2 * p + 1]] = v1;
        }
}

// ---------------- vector quantize + q materialization (gather fused) ----------------
__global__ void vq_k(const float* __restrict__ emb, const float* __restrict__ z,
                     float* __restrict__ q) {
    extern __shared__ float sm[];
    // paired codebook: float4 at (pair, j2) = {e[2k][2j2], e[2k+1][2j2], e[2k][2j2+1], e[2k+1][2j2+1]}
    float4* sp4 = (float4*)sm;               // 256*32 float4
    float2* sn2 = (float2*)(sm + 512 * 64);  // 256 norm pairs
    for (int i = threadIdx.x; i < 512 * 64; i += blockDim.x) {
        int k = i >> 6, j = i & 63;
        int dst = ((k >> 1) * 32 + (j >> 1)) * 4 + (j & 1) * 2 + (k & 1);
        sm[dst] = emb[i];
    }
    __syncthreads();
    for (int kp = threadIdx.x; kp < 256; kp += blockDim.x) {
        float sx = 0.0f, sy = 0.0f;
#pragma unroll
        for (int j2 = 0; j2 < 32; j2++) {
            float4 e = sp4[kp * 32 + j2];
            sx += e.x * e.x + e.z * e.z;
            sy += e.y * e.y + e.w * e.w;
        }
        sn2[kp] = make_float2(sx, sy);
    }
    __syncthreads();

    int n = blockIdx.x * blockDim.x + threadIdx.x;
    int b  = n >> 12;
    int hw = n & 4095;
    const float* zp = z + (size_t)b * 262144 + hw;
    float zr[64];
#pragma unroll
    for (int j = 0; j < 64; j++) zr[j] = zp[(size_t)j * 4096];

    float best = 3.4e38f;
    int bi = 0;
    for (int kp = 0; kp < 256; kp++) {
        const float4* ep = sp4 + kp * 32;
        unsigned long long dp = pk(0.0f, 0.0f);
#pragma unroll
        for (int j2 = 0; j2 < 32; j2++) {
            float4 e = ep[j2];
            fma2(dp, pk2(zr[2 * j2]),     pk(e.x, e.y));
            fma2(dp, pk2(zr[2 * j2 + 1]), pk(e.z, e.w));
        }
        float2 d2 = up2(dp);
        float2 nn = sn2[kp];
        float dx = nn.x - 2.0f * d2.x;
        if (dx < best) { best = dx; bi = 2 * kp; }
        float dy = nn.y - 2.0f * d2.y;
        if (dy < best) { best = dy; bi = 2 * kp + 1; }
    }

    // write q (NCHW, coalesced per channel: consecutive threads = consecutive hw),
    // tf32-rounded for the dc1 mma consumer; loss uses exact codebook values.
    float* qp = q + (size_t)b * 262144 + hw;
    float ls = 0.0f;
#pragma unroll
    for (int j = 0; j < 64; j++) {
        float e = sm[((bi >> 1) * 32 + (j >> 1)) * 4 + (j & 1) * 2 + (bi & 1)];
        qp[(size_t)j * 4096] = cvt_tf32(e);
        float df = e - zr[j];
        ls += df * df;
    }
#pragma unroll
    for (int o = 16; o > 0; o >>= 1) ls += __shfl_xor_sync(0xffffffffu, ls, o);
    if ((threadIdx.x & 31) == 0) atomicAdd(&g_loss, ls);
}

// ---------------- host ----------------
static float* sym_addr(const void* sym) {
    void* p = nullptr;
    cudaGetSymbolAddress(&p, sym);
    return (float*)p;
}

extern "C" void kernel_launch(void* const* d_in, const int* in_sizes, int n_in,
                              void* d_out, int out_size) {
    const float* x   = (const float*)d_in[0];
    const float* w1  = (const float*)d_in[1];
    const float* b1  = (const float*)d_in[2];
    const float* w2  = (const float*)d_in[3];
    const float* b2  = (const float*)d_in[4];
    const float* w3  = (const float*)d_in[5];
    const float* b3  = (const float*)d_in[6];
    const float* emb = (const float*)d_in[7];
    const float* dw1 = (const float*)d_in[8];
    const float* db1 = (const float*)d_in[9];
    const float* dw2 = (const float*)d_in[10];
    const float* db2 = (const float*)d_in[11];
    const float* dw3 = (const float*)d_in[12];
    const float* db3 = (const float*)d_in[13];
    float* out = (float*)d_out;

    float*  h1   = sym_addr(g_h1);
    float*  h2   = sym_addr(g_h2);
    float*  z    = sym_addr(g_z);
    float*  q    = sym_addr(g_q);
    float*  d1   = sym_addr(g_d1);
    float*  d2   = sym_addr(g_d2);
    float*  wt1  = sym_addr(g_wt1);
    float*  wt3d = sym_addr(g_wt3d);
    float2* pw1f = (float2*)sym_addr(g_pw1f);
    float2* pw2f = (float2*)sym_addr(g_pw2f);
    float2* cw2f = (float2*)sym_addr(g_cw2f);
    float2* cw3f = (float2*)sym_addr(g_cw3f);

    auto c1  = conv_f2_k<3, 4, 64, 32, 2, 256, 256, 128, 128, 2, 1, true>;
    auto c2m = conv2_mma_k<64, 128, 128, 128, 4, true>;
    auto c3m = conv3_mma_k<128, 64, 64, 8>;
    auto dc1 = deconv_mma_k<64, 128, 2, 64, 80, 64, 64, 8, true>;
    auto dc2 = deconv_mma_k<128, 64, 1, 128, 144, 128, 128, 8, false>;
    auto dc3 = conv_sig_k<64, 3, 3, 4, 256, 256, 1>;

    // smem sizes
    const int smem_c2  = 2 * (4 * 6 * 130) * 4 + 2 * (4 * 2 * 16 * 32) * 8;  // 90496
    const int smem_c3  = 2 * (8 * 4 * 80) * 4 + 2 * (4 * 3 * 8 * 32) * 8;    // 69632
    const int smem_dc1 = 2 * (8 * 3 * 80) * 4 + 2 * (4 * 16 * 32) * 8;       // 48128
    const int smem_dc2 = 2 * (8 * 2 * 144) * 4 + 2 * (4 * 8 * 32) * 8;       // 34816
    const int smem_vq  = 512 * 64 * 4 + 256 * 8;                             // 133120

    cudaFuncSetAttribute(c2m, cudaFuncAttributeMaxDynamicSharedMemorySize, smem_c2);
    cudaFuncSetAttribute(c3m, cudaFuncAttributeMaxDynamicSharedMemorySize, smem_c3);
    cudaFuncSetAttribute(dc1, cudaFuncAttributeMaxDynamicSharedMemorySize, smem_dc1);
    cudaFuncSetAttribute(dc2, cudaFuncAttributeMaxDynamicSharedMemorySize, smem_dc2);
    cudaFuncSetAttribute(vq_k, cudaFuncAttributeMaxDynamicSharedMemorySize, smem_vq);

    // launch 1: fused repack (+ loss zero). total indices = 217792
    repack_all_k<<<(217792 + 255) / 256, 256>>>(w1, w2, w3, dw1, dw2, dw3,
                                                wt1, cw2f, cw3f, pw1f, pw2f, wt3d);

    // launch 2-4: encoder
    c1<<<dim3(1024, 2), 256, 3 * 16 * 32 * 4>>>(x, wt1, b1, h1);
    c2m<<<dim3(32 * 32), 256, smem_c2>>>(h1, cw2f, b2, h2);
    c3m<<<dim3(32 * 32), 256, smem_c3>>>(h2, cw3f, b3, z);

    // launch 5: vector quantize (writes q directly)
    vq_k<<<512, 256, smem_vq>>>(emb, z, q);

    // launch 6-8: decoder (parity on blockIdx.x -> wave-adjacent, L2-hot input)
    dc1<<<dim3(4, 32 * 32), 256, smem_dc1>>>(q, pw1f, db1, d1);
    dc2<<<dim3(4, 128 * 32), 256, smem_dc2>>>(d1, pw2f, db2, d2);
    dc3<<<dim3(2048, 1), 256, 64 * 9 * 3 * 4>>>(d2, wt3d, db3, out);

    finalize_k<<<1, 1>>>(out, out_size - 1);
}